// round 5
// baseline (speedup 1.0000x reference)
#include <cuda_runtime.h>
#include <cstdint>

#define NB 4
#define CC 64
#define SS 65536    // H*W
#define NS 262144   // NB*SS

// ---------------- scratch ----------------
__device__ float g_Yk[(size_t)NS * CC];   // pixel-major [N,S,C]
__device__ float g_Yq[(size_t)NS * CC];
__device__ float g_Yv[(size_t)NS * CC];
__device__ float g_off[(size_t)6 * NS];   // (ky,kx,qy,qx,vy,vx)
__device__ float g_ctxp[1024 * 1024];     // per-block ctx partials
__device__ float g_zp[1024 * 64];         // per-block Z partials
__device__ float g_ctx[NB * 1024];        // ctx [n][h][k][v]
__device__ float g_Z[NB * 64];
__device__ float g_B[NB * 64 * 64];       // folded matrix [n][o][kk]

// ---------------- packed f32x2 helpers ----------------
typedef unsigned long long ull;
__device__ __forceinline__ ull pk2(float lo, float hi) {
    ull r; asm("mov.b64 %0, {%1, %2};" : "=l"(r) : "f"(lo), "f"(hi)); return r;
}
__device__ __forceinline__ void upk2(ull v, float& lo, float& hi) {
    asm("mov.b64 {%0, %1}, %2;" : "=f"(lo), "=f"(hi) : "l"(v));
}
__device__ __forceinline__ ull fma2(ull a, ull b, ull c) {
    ull d; asm("fma.rn.f32x2 %0, %1, %2, %3;" : "=l"(d) : "l"(a), "l"(b), "l"(c)); return d;
}

// =============== K_A: offsets + 3 projections, 128-px tile ===============
// 256 threads. GEMM: each thread 8 outputs x 4 pixels.
__global__ __launch_bounds__(256) void k_a(
    const float* __restrict__ x,
    const float* __restrict__ kow, const float* __restrict__ kob, const float* __restrict__ kw,
    const float* __restrict__ qow, const float* __restrict__ qob, const float* __restrict__ qw,
    const float* __restrict__ vow, const float* __restrict__ vob, const float* __restrict__ vw) {
    __shared__ float xs[64][128];  // [c][p]  32KB
    __shared__ float ws[64][64];   // [c][o]  16KB (also unioned: offset weights)

    int tid = threadIdx.x;
    int pg0 = blockIdx.x * 128;               // 2048 blocks
    int n   = pg0 >> 16;
    int sIn = pg0 & 65535;

    float* owbuf = &ws[0][0];                 // ow[d][c] = owbuf[d*64+c] (384 floats)

    const float* xb = x + (size_t)n * CC * SS + sIn;
#pragma unroll
    for (int it = 0; it < 32; it++) {
        int idx = tid + 256 * it;
        int c = idx >> 7, p = idx & 127;
        xs[c][p] = xb[(size_t)c * SS + p];
    }
    if (tid < 128) owbuf[tid] = kow[tid];
    else if (tid < 256) owbuf[128 + (tid - 128)] = qow[tid - 128];
    if (tid < 128) owbuf[256 + tid] = vow[tid];
    __syncthreads();

    // ---- offsets: 128 pixels x 2 halves
    {
        int p = tid >> 1, half = tid & 1;
        float od[6] = {0.f, 0.f, 0.f, 0.f, 0.f, 0.f};
#pragma unroll
        for (int i = 0; i < 32; i++) {
            int c = half * 32 + i;
            float xv = xs[c][p];
#pragma unroll
            for (int d = 0; d < 6; d++) od[d] += xv * owbuf[d * 64 + c];
        }
#pragma unroll
        for (int d = 0; d < 6; d++) od[d] += __shfl_xor_sync(0xffffffffu, od[d], 1);
        if (half == 0) {
            float ob[6] = {kob[0], kob[1], qob[0], qob[1], vob[0], vob[1]};
#pragma unroll
            for (int d = 0; d < 6; d++)
                g_off[(size_t)d * NS + pg0 + p] = od[d] + ob[d];
        }
    }

    const float* wp3[3] = {kw, qw, vw};
    float* yd3[3] = {g_Yk, g_Yq, g_Yv};
    int og = tid >> 5;   // 0..7  -> outputs og*8..og*8+7
    int pg = tid & 31;   // 0..31 -> pixels pg*4..pg*4+3

    for (int pr = 0; pr < 3; pr++) {
        __syncthreads();
        const float* wp = wp3[pr];
#pragma unroll
        for (int it = 0; it < 16; it++) {
            int idx = tid + 256 * it;
            int o = idx >> 6, c = idx & 63;
            ws[c][o] = wp[idx];
        }
        __syncthreads();

        ull acc[4][4];   // [output-pair j][pixel i]
#pragma unroll
        for (int j = 0; j < 4; j++)
#pragma unroll
            for (int i = 0; i < 4; i++) acc[j][i] = pk2(0.f, 0.f);

#pragma unroll 4
        for (int c = 0; c < 64; c++) {
            float4 xq = *(const float4*)&xs[c][pg * 4];
            ull xd[4] = {pk2(xq.x, xq.x), pk2(xq.y, xq.y),
                         pk2(xq.z, xq.z), pk2(xq.w, xq.w)};
            float4 wa = *(const float4*)&ws[c][og * 8];
            float4 wb = *(const float4*)&ws[c][og * 8 + 4];
            ull wd[4] = {pk2(wa.x, wa.y), pk2(wa.z, wa.w),
                         pk2(wb.x, wb.y), pk2(wb.z, wb.w)};
#pragma unroll
            for (int j = 0; j < 4; j++)
#pragma unroll
                for (int i = 0; i < 4; i++)
                    acc[j][i] = fma2(wd[j], xd[i], acc[j][i]);
        }

        // epilogue: pixel-major [p][c]
        float* yb = yd3[pr] + (size_t)pg0 * 64;
#pragma unroll
        for (int i = 0; i < 4; i++) {
            int p = pg * 4 + i;
            float a0, a1, a2, a3, a4, a5, a6, a7;
            upk2(acc[0][i], a0, a1); upk2(acc[1][i], a2, a3);
            upk2(acc[2][i], a4, a5); upk2(acc[3][i], a6, a7);
            float* dst = yb + (size_t)p * 64 + og * 8;
            *(float4*)dst       = make_float4(a0, a1, a2, a3);
            *(float4*)(dst + 4) = make_float4(a4, a5, a6, a7);
        }
    }
}

// =============== K_B: gather K,V + exp + context/Z partials ===============
// grid 1024; 4 tiles of 64 px per block.
__global__ __launch_bounds__(256) void k_b() {
    __shared__ float Ke[64][68];
    __shared__ float Vs[64][68];

    int tid = threadIdx.x;
    int h = tid >> 6, k = (tid >> 2) & 15, vg = tid & 3;
    int p4 = tid >> 2, qd = tid & 3;

    float a0 = 0.f, a1 = 0.f, a2 = 0.f, a3 = 0.f, z = 0.f;

    for (int tile = 0; tile < 4; tile++) {
        int pg0 = (blockIdx.x * 4 + tile) * 64;
        int n   = pg0 >> 16;
        int sIn = pg0 & 65535;
        long pG = (long)pg0 + p4;
        int s   = sIn + p4;
        int yI  = s >> 8, xI = s & 255;

#pragma unroll
        for (int tv = 0; tv < 2; tv++) {
            const float* Ysrc = tv ? g_Yv : g_Yk;
            int dB = tv ? 4 : 0;
            float oy = g_off[(size_t)dB * NS + pG];
            float ox = g_off[(size_t)(dB + 1) * NS + pG];
            float py = (float)yI + oy, px = (float)xI + ox;
            float y0f = floorf(py), x0f = floorf(px);
            int iy0 = (int)y0f, ix0 = (int)x0f;
            float ty = py - y0f, tx = px - x0f;
            float wg[4] = {(1.f - ty) * (1.f - tx), (1.f - ty) * tx,
                           ty * (1.f - tx), ty * tx};
            float4 acc[4];
#pragma unroll
            for (int i = 0; i < 4; i++) acc[i] = make_float4(0.f, 0.f, 0.f, 0.f);
#pragma unroll
            for (int t = 0; t < 4; t++) {
                int iy = iy0 + (t >> 1), ix = ix0 + (t & 1);
                if (iy >= 0 && iy < 256 && ix >= 0 && ix < 256) {
                    const float4* tp = (const float4*)(Ysrc +
                        ((((size_t)n << 16) | ((size_t)iy << 8) | (size_t)ix) * 64) + qd * 16);
                    float w = wg[t];
#pragma unroll
                    for (int i = 0; i < 4; i++) {
                        float4 v = tp[i];
                        acc[i].x += w * v.x; acc[i].y += w * v.y;
                        acc[i].z += w * v.z; acc[i].w += w * v.w;
                    }
                }
            }
            if (tv == 0) {
#pragma unroll
                for (int i = 0; i < 4; i++) {
                    acc[i].x = __expf(acc[i].x); acc[i].y = __expf(acc[i].y);
                    acc[i].z = __expf(acc[i].z); acc[i].w = __expf(acc[i].w);
                    *(float4*)&Ke[p4][qd * 16 + 4 * i] = acc[i];
                }
            } else {
#pragma unroll
                for (int i = 0; i < 4; i++)
                    *(float4*)&Vs[p4][qd * 16 + 4 * i] = acc[i];
            }
        }
        __syncthreads();

#pragma unroll 8
        for (int p = 0; p < 64; p++) {
            float kv = Ke[p][h * 16 + k];
            float4 v4 = *(const float4*)&Vs[p][h * 16 + vg * 4];
            a0 += kv * v4.x; a1 += kv * v4.y; a2 += kv * v4.z; a3 += kv * v4.w;
            z += kv;
        }
        __syncthreads();
    }

    size_t base = (size_t)blockIdx.x * 1024 + h * 256 + k * 16 + vg * 4;
    g_ctxp[base + 0] = a0; g_ctxp[base + 1] = a1;
    g_ctxp[base + 2] = a2; g_ctxp[base + 3] = a3;
    if (vg == 0) g_zp[blockIdx.x * 64 + h * 16 + k] = z;
}

// =============== reduce partials: warp per row, 256 partial blocks per n ======
__global__ __launch_bounds__(256) void k_red2() {
    int wid = threadIdx.x >> 5, lid = threadIdx.x & 31;
    if (blockIdx.x < 512) {
        int row = blockIdx.x * 8 + wid;            // 4096 ctx rows
        int n = row >> 10, idx = row & 1023;
        float v = 0.f;
#pragma unroll
        for (int j = 0; j < 8; j++)
            v += g_ctxp[((size_t)(n * 256 + j * 32 + lid)) * 1024 + idx];
#pragma unroll
        for (int o = 16; o > 0; o >>= 1) v += __shfl_xor_sync(0xffffffffu, v, o);
        if (lid == 0) g_ctx[row] = v;
    } else {
        int zrow = (blockIdx.x - 512) * 8 + wid;   // 256 z rows
        int n = zrow >> 6, kk = zrow & 63;
        float v = 0.f;
#pragma unroll
        for (int j = 0; j < 8; j++)
            v += g_zp[(n * 256 + j * 32 + lid) * 64 + kk];
#pragma unroll
        for (int o = 16; o > 0; o >>= 1) v += __shfl_xor_sync(0xffffffffu, v, o);
        if (lid == 0) g_Z[zrow] = v;
    }
}

// =============== fold: B[n][o][kk] ===============
__global__ __launch_bounds__(256) void k_fold2(const float* __restrict__ rpw) {
    int idx = blockIdx.x * 256 + threadIdx.x;    // 16384 outputs
    int n = idx >> 12, o = (idx >> 6) & 63, kk = idx & 63;
    int h = kk >> 4, k = kk & 15;
    const float* cx = g_ctx + n * 1024 + h * 256 + k * 16;
    const float* wr = rpw + o * 64 + h * 16;
    float a = 0.f;
#pragma unroll
    for (int v = 0; v < 16; v++) a += wr[v] * cx[v];
    g_B[n * 4096 + (o << 6) + kk] = a / g_Z[n * 64 + kk];
}

// =============== K_C: gather Q + channel softmax + B-GEMM + bias ===============
// 256 threads, 128-px tile.
__global__ __launch_bounds__(256) void k_c(const float* __restrict__ rpb,
                                           float* __restrict__ out) {
    __shared__ float qs[64][128];  // [kk][p] 32KB
    __shared__ float bu[64][64];   // B transposed [kk][o] 16KB

    int tid = threadIdx.x;
    int pg0 = blockIdx.x * 128;                // 2048 blocks
    int n   = pg0 >> 16;
    int sIn = pg0 & 65535;

    const float* Bn = g_B + (size_t)n * 4096;
#pragma unroll
    for (int it = 0; it < 16; it++) {
        int idx = tid + 256 * it;
        int o = idx >> 6, kk = idx & 63;
        bu[kk][o] = Bn[idx];
    }

    // ---- gather q: 128 px x 2 halves of 32 channels
    {
        int p2 = tid >> 1, qh = tid & 1;
        long pG = (long)pg0 + p2;
        int s = sIn + p2;
        int yI = s >> 8, xI = s & 255;
        float oy = g_off[(size_t)2 * NS + pG];
        float ox = g_off[(size_t)3 * NS + pG];
        float py = (float)yI + oy, px = (float)xI + ox;
        float y0f = floorf(py), x0f = floorf(px);
        int iy0 = (int)y0f, ix0 = (int)x0f;
        float ty = py - y0f, tx = px - x0f;
        float wg[4] = {(1.f - ty) * (1.f - tx), (1.f - ty) * tx,
                       ty * (1.f - tx), ty * tx};
        float acc[32];
#pragma unroll
        for (int i = 0; i < 32; i++) acc[i] = 0.f;
#pragma unroll
        for (int t = 0; t < 4; t++) {
            int iy = iy0 + (t >> 1), ix = ix0 + (t & 1);
            if (iy >= 0 && iy < 256 && ix >= 0 && ix < 256) {
                const float4* tp = (const float4*)(g_Yq +
                    ((((size_t)n << 16) | ((size_t)iy << 8) | (size_t)ix) * 64) + qh * 32);
                float w = wg[t];
#pragma unroll
                for (int i = 0; i < 8; i++) {
                    float4 v = tp[i];
                    acc[4 * i + 0] += w * v.x; acc[4 * i + 1] += w * v.y;
                    acc[4 * i + 2] += w * v.z; acc[4 * i + 3] += w * v.w;
                }
            }
        }
#pragma unroll
        for (int i = 0; i < 32; i++) qs[qh * 32 + i][p2] = acc[i];
    }
    __syncthreads();

    // ---- channel softmax per head: each thread 2 heads of one pixel
    {
        int p = tid >> 1, hb = (tid & 1) * 2;
#pragma unroll
        for (int hh = 0; hh < 2; hh++) {
            int h0 = hb + hh;
            float v[16];
#pragma unroll
            for (int i = 0; i < 16; i++) v[i] = qs[h0 * 16 + i][p];
            float m = v[0];
#pragma unroll
            for (int i = 1; i < 16; i++) m = fmaxf(m, v[i]);
            float sum = 0.f;
#pragma unroll
            for (int i = 0; i < 16; i++) { v[i] = __expf(v[i] - m); sum += v[i]; }
            float inv = 1.f / sum;
#pragma unroll
            for (int i = 0; i < 16; i++) qs[h0 * 16 + i][p] = v[i] * inv;
        }
    }
    __syncthreads();

    // ---- GEMM out = B · q_sm : 8 outputs x 4 pixels per thread
    int og = tid >> 5;   // 0..7
    int pg = tid & 31;   // 0..31
    ull acc[4][4];
#pragma unroll
    for (int j = 0; j < 4; j++)
#pragma unroll
        for (int i = 0; i < 4; i++) acc[j][i] = pk2(0.f, 0.f);

#pragma unroll 4
    for (int c = 0; c < 64; c++) {
        float4 xq = *(const float4*)&qs[c][pg * 4];
        ull xd[4] = {pk2(xq.x, xq.x), pk2(xq.y, xq.y),
                     pk2(xq.z, xq.z), pk2(xq.w, xq.w)};
        float4 wa = *(const float4*)&bu[c][og * 8];
        float4 wb = *(const float4*)&bu[c][og * 8 + 4];
        ull wd[4] = {pk2(wa.x, wa.y), pk2(wa.z, wa.w),
                     pk2(wb.x, wb.y), pk2(wb.z, wb.w)};
#pragma unroll
        for (int j = 0; j < 4; j++)
#pragma unroll
            for (int i = 0; i < 4; i++)
                acc[j][i] = fma2(wd[j], xd[i], acc[j][i]);
    }

    // epilogue: channel-major out[N,C,H,W]; float4 over 4 pixels per channel
#pragma unroll
    for (int j = 0; j < 4; j++) {
        int c0 = og * 8 + 2 * j;
        float b0 = rpb[c0], b1 = rpb[c0 + 1];
        float l0, h0, l1, h1, l2, h2, l3, h3;
        upk2(acc[j][0], l0, h0); upk2(acc[j][1], l1, h1);
        upk2(acc[j][2], l2, h2); upk2(acc[j][3], l3, h3);
        float* d0 = out + ((size_t)(n * 64 + c0)) * SS + sIn + pg * 4;
        float* d1 = out + ((size_t)(n * 64 + c0 + 1)) * SS + sIn + pg * 4;
        *(float4*)d0 = make_float4(l0 + b0, l1 + b0, l2 + b0, l3 + b0);
        *(float4*)d1 = make_float4(h0 + b1, h1 + b1, h2 + b1, h3 + b1);
    }
}

// ---------------- launch ----------------
extern "C" void kernel_launch(void* const* d_in, const int* in_sizes, int n_in,
                              void* d_out, int out_size) {
    const float* x   = (const float*)d_in[0];
    const float* kow = (const float*)d_in[1];
    const float* kob = (const float*)d_in[2];
    const float* kw  = (const float*)d_in[3];
    const float* qow = (const float*)d_in[4];
    const float* qob = (const float*)d_in[5];
    const float* qw  = (const float*)d_in[6];
    const float* vow = (const float*)d_in[7];
    const float* vob = (const float*)d_in[8];
    const float* vw  = (const float*)d_in[9];
    const float* rpw = (const float*)d_in[10];
    const float* rpb = (const float*)d_in[11];
    float* out = (float*)d_out;

    k_a<<<NS / 128, 256>>>(x, kow, kob, kw, qow, qob, qw, vow, vob, vw);
    k_b<<<1024, 256>>>();
    k_red2<<<544, 256>>>();
    k_fold2<<<64, 256>>>(rpw);
    k_c<<<NS / 128, 256>>>(rpb, out);
}

// round 6
// speedup vs baseline: 1.2196x; 1.2196x over previous
#include <cuda_runtime.h>
#include <cstdint>

#define NB 4
#define CC 64
#define SS 65536    // H*W
#define NS 262144   // NB*SS

// ---------------- scratch ----------------
__device__ float g_Yk[(size_t)NS * CC];   // pixel-major [N,S,C]
__device__ float g_Yq[(size_t)NS * CC];
__device__ float g_Yv[(size_t)NS * CC];
__device__ float g_off[(size_t)6 * NS];   // (ky,kx,qy,qx,vy,vx)
__device__ float g_ctxp[1024 * 1024];     // per-block ctx partials
__device__ float g_zp[1024 * 64];         // per-block Z partials
__device__ float g_ctx[NB * 1024];        // ctx [n][h][k][v]
__device__ float g_Z[NB * 64];
__device__ float g_B[NB * 64 * 64];       // folded matrix [n][o][kk]

// ---------------- packed f32x2 helpers ----------------
typedef unsigned long long ull;
__device__ __forceinline__ ull pk2(float lo, float hi) {
    ull r; asm("mov.b64 %0, {%1, %2};" : "=l"(r) : "f"(lo), "f"(hi)); return r;
}
__device__ __forceinline__ void upk2(ull v, float& lo, float& hi) {
    asm("mov.b64 {%0, %1}, %2;" : "=f"(lo), "=f"(hi) : "l"(v));
}
__device__ __forceinline__ ull fma2(ull a, ull b, ull c) {
    ull d; asm("fma.rn.f32x2 %0, %1, %2, %3;" : "=l"(d) : "l"(a), "l"(b), "l"(c)); return d;
}

// =============== K_A: offsets + 3 projections, dense fma2 GEMM ===============
// 128 threads, 64-pixel tile. Each thread: 8 outputs x 4 pixels.
__global__ __launch_bounds__(128) void k_a(
    const float* __restrict__ x,
    const float* __restrict__ kow, const float* __restrict__ kob, const float* __restrict__ kw,
    const float* __restrict__ qow, const float* __restrict__ qob, const float* __restrict__ qw,
    const float* __restrict__ vow, const float* __restrict__ vob, const float* __restrict__ vw) {
    __shared__ float xs[64][68];   // [c][p]
    __shared__ float ws[64][68];   // [c][o]
    __shared__ float ow_s[6][64];
    __shared__ float ob_s[6];

    int tid = threadIdx.x;
    int pg0 = blockIdx.x * 64;
    int n   = pg0 >> 16;
    int sIn = pg0 & 65535;

    const float* xb = x + (size_t)n * CC * SS + sIn;
#pragma unroll
    for (int it = 0; it < 32; it++) {
        int idx = tid + 128 * it;
        int c = idx >> 6, p = idx & 63;
        xs[c][p] = xb[(size_t)c * SS + p];
    }
    if (tid < 128) ow_s[0 + (tid >> 6)][tid & 63] = kow[tid];
    if (tid < 128) ow_s[2 + (tid >> 6)][tid & 63] = qow[tid];
    if (tid < 128) ow_s[4 + (tid >> 6)][tid & 63] = vow[tid];
    if (tid < 2) { ob_s[tid] = kob[tid]; ob_s[2 + tid] = qob[tid]; ob_s[4 + tid] = vob[tid]; }
    __syncthreads();

    // ---- offsets: 64 pixels x 2 halves
    {
        int p = tid >> 1, half = tid & 1;
        float od[6] = {0.f, 0.f, 0.f, 0.f, 0.f, 0.f};
#pragma unroll
        for (int i = 0; i < 32; i++) {
            int c = half * 32 + i;
            float xv = xs[c][p];
#pragma unroll
            for (int d = 0; d < 6; d++) od[d] += xv * ow_s[d][c];
        }
#pragma unroll
        for (int d = 0; d < 6; d++) od[d] += __shfl_xor_sync(0xffffffffu, od[d], 1);
        if (half == 0) {
#pragma unroll
            for (int d = 0; d < 6; d++)
                g_off[(size_t)d * NS + pg0 + p] = od[d] + ob_s[d];
        }
    }

    const float* wp3[3] = {kw, qw, vw};
    float* yd3[3] = {g_Yk, g_Yq, g_Yv};
    int og = tid >> 4;   // 0..7  -> outputs og*8..og*8+7
    int pg = tid & 15;   // 0..15 -> pixels pg*4..pg*4+3

    for (int pr = 0; pr < 3; pr++) {
        __syncthreads();
        const float* wp = wp3[pr];
#pragma unroll
        for (int it = 0; it < 32; it++) {
            int idx = tid + 128 * it;
            int o = idx >> 6, c = idx & 63;
            ws[c][o] = wp[idx];
        }
        __syncthreads();

        ull acc[4][4];   // [output-pair j][pixel i]
#pragma unroll
        for (int j = 0; j < 4; j++)
#pragma unroll
            for (int i = 0; i < 4; i++) acc[j][i] = pk2(0.f, 0.f);

#pragma unroll 4
        for (int c = 0; c < 64; c++) {
            float2 x01 = *(const float2*)&xs[c][pg * 4];
            float2 x23 = *(const float2*)&xs[c][pg * 4 + 2];
            ull xd[4] = {pk2(x01.x, x01.x), pk2(x01.y, x01.y),
                         pk2(x23.x, x23.x), pk2(x23.y, x23.y)};
            float4 wa = *(const float4*)&ws[c][og * 8];
            float4 wb = *(const float4*)&ws[c][og * 8 + 4];
            ull wd[4] = {pk2(wa.x, wa.y), pk2(wa.z, wa.w),
                         pk2(wb.x, wb.y), pk2(wb.z, wb.w)};
#pragma unroll
            for (int j = 0; j < 4; j++)
#pragma unroll
                for (int i = 0; i < 4; i++)
                    acc[j][i] = fma2(wd[j], xd[i], acc[j][i]);
        }

        // epilogue: pixel-major [p][c]; per pixel 8 consecutive outputs = 2 float4
        float* yb = yd3[pr] + (size_t)pg0 * 64;
#pragma unroll
        for (int i = 0; i < 4; i++) {
            int p = pg * 4 + i;
            float a0, a1, a2, a3, a4, a5, a6, a7;
            upk2(acc[0][i], a0, a1); upk2(acc[1][i], a2, a3);
            upk2(acc[2][i], a4, a5); upk2(acc[3][i], a6, a7);
            float* dst = yb + (size_t)p * 64 + og * 8;
            *(float4*)dst       = make_float4(a0, a1, a2, a3);
            *(float4*)(dst + 4) = make_float4(a4, a5, a6, a7);
        }
    }
}

// =============== K_B: gather K,V + exp + context/Z partials ===============
// grid 1024; 4 tiles of 64 px per block.
__global__ __launch_bounds__(256) void k_b() {
    __shared__ float Ke[64][68];
    __shared__ float Vs[64][68];

    int tid = threadIdx.x;
    int h = tid >> 6, k = (tid >> 2) & 15, vg = tid & 3;
    int p4 = tid >> 2, qd = tid & 3;

    float a0 = 0.f, a1 = 0.f, a2 = 0.f, a3 = 0.f, z = 0.f;

    for (int tile = 0; tile < 4; tile++) {
        int pg0 = (blockIdx.x * 4 + tile) * 64;
        int n   = pg0 >> 16;
        int sIn = pg0 & 65535;
        long pG = (long)pg0 + p4;
        int s   = sIn + p4;
        int yI  = s >> 8, xI = s & 255;

#pragma unroll
        for (int tv = 0; tv < 2; tv++) {
            const float* Ysrc = tv ? g_Yv : g_Yk;
            int dB = tv ? 4 : 0;
            float oy = g_off[(size_t)dB * NS + pG];
            float ox = g_off[(size_t)(dB + 1) * NS + pG];
            float py = (float)yI + oy, px = (float)xI + ox;
            float y0f = floorf(py), x0f = floorf(px);
            int iy0 = (int)y0f, ix0 = (int)x0f;
            float ty = py - y0f, tx = px - x0f;
            float wg[4] = {(1.f - ty) * (1.f - tx), (1.f - ty) * tx,
                           ty * (1.f - tx), ty * tx};
            float4 acc[4];
#pragma unroll
            for (int i = 0; i < 4; i++) acc[i] = make_float4(0.f, 0.f, 0.f, 0.f);
#pragma unroll
            for (int t = 0; t < 4; t++) {
                int iy = iy0 + (t >> 1), ix = ix0 + (t & 1);
                if (iy >= 0 && iy < 256 && ix >= 0 && ix < 256) {
                    const float4* tp = (const float4*)(Ysrc +
                        ((((size_t)n << 16) | ((size_t)iy << 8) | (size_t)ix) * 64) + qd * 16);
                    float w = wg[t];
#pragma unroll
                    for (int i = 0; i < 4; i++) {
                        float4 v = tp[i];
                        acc[i].x += w * v.x; acc[i].y += w * v.y;
                        acc[i].z += w * v.z; acc[i].w += w * v.w;
                    }
                }
            }
            if (tv == 0) {
#pragma unroll
                for (int i = 0; i < 4; i++) {
                    acc[i].x = __expf(acc[i].x); acc[i].y = __expf(acc[i].y);
                    acc[i].z = __expf(acc[i].z); acc[i].w = __expf(acc[i].w);
                    *(float4*)&Ke[p4][qd * 16 + 4 * i] = acc[i];
                }
            } else {
#pragma unroll
                for (int i = 0; i < 4; i++)
                    *(float4*)&Vs[p4][qd * 16 + 4 * i] = acc[i];
            }
        }
        __syncthreads();

#pragma unroll 8
        for (int p = 0; p < 64; p++) {
            float kv = Ke[p][h * 16 + k];
            float4 v4 = *(const float4*)&Vs[p][h * 16 + vg * 4];
            a0 += kv * v4.x; a1 += kv * v4.y; a2 += kv * v4.z; a3 += kv * v4.w;
            z += kv;
        }
        __syncthreads();
    }

    size_t base = (size_t)blockIdx.x * 1024 + h * 256 + k * 16 + vg * 4;
    g_ctxp[base + 0] = a0; g_ctxp[base + 1] = a1;
    g_ctxp[base + 2] = a2; g_ctxp[base + 3] = a3;
    if (vg == 0) g_zp[blockIdx.x * 64 + h * 16 + k] = z;
}

// =============== reduce partials: warp per row, 256 partial blocks per n ======
__global__ __launch_bounds__(256) void k_red2() {
    int wid = threadIdx.x >> 5, lid = threadIdx.x & 31;
    if (blockIdx.x < 512) {
        int row = blockIdx.x * 8 + wid;            // 4096 ctx rows
        int n = row >> 10, idx = row & 1023;
        float v = 0.f;
#pragma unroll
        for (int j = 0; j < 8; j++)
            v += g_ctxp[((size_t)(n * 256 + j * 32 + lid)) * 1024 + idx];
#pragma unroll
        for (int o = 16; o > 0; o >>= 1) v += __shfl_xor_sync(0xffffffffu, v, o);
        if (lid == 0) g_ctx[row] = v;
    } else {
        int zrow = (blockIdx.x - 512) * 8 + wid;   // 256 z rows
        int n = zrow >> 6, kk = zrow & 63;
        float v = 0.f;
#pragma unroll
        for (int j = 0; j < 8; j++)
            v += g_zp[(n * 256 + j * 32 + lid) * 64 + kk];
#pragma unroll
        for (int o = 16; o > 0; o >>= 1) v += __shfl_xor_sync(0xffffffffu, v, o);
        if (lid == 0) g_Z[zrow] = v;
    }
}

// =============== fold: B[n][o][kk] ===============
__global__ __launch_bounds__(256) void k_fold2(const float* __restrict__ rpw) {
    int idx = blockIdx.x * 256 + threadIdx.x;    // 16384 outputs
    int n = idx >> 12, o = (idx >> 6) & 63, kk = idx & 63;
    int h = kk >> 4, k = kk & 15;
    const float* cx = g_ctx + n * 1024 + h * 256 + k * 16;
    const float* wr = rpw + o * 64 + h * 16;
    float a = 0.f;
#pragma unroll
    for (int v = 0; v < 16; v++) a += wr[v] * cx[v];
    g_B[n * 4096 + (o << 6) + kk] = a / g_Z[n * 64 + kk];
}

// =============== K_C: gather Q + channel softmax + B-GEMM + bias ===============
// 128 threads, 64-pixel tile. Each thread: 8 output channels x 4 pixels.
__global__ __launch_bounds__(128) void k_c(const float* __restrict__ rpb,
                                           float* __restrict__ out) {
    __shared__ float qs[64][68];   // [kk][p]
    __shared__ float bu[64][68];   // B transposed [kk][o]
    __shared__ float bias_s[64];

    int tid = threadIdx.x;
    int pg0 = blockIdx.x * 64;
    int n   = pg0 >> 16;
    int sIn = pg0 & 65535;

    const float* Bn = g_B + (size_t)n * 4096;
#pragma unroll
    for (int it = 0; it < 32; it++) {
        int idx = tid + 128 * it;
        int o = idx >> 6, kk = idx & 63;
        bu[kk][o] = Bn[idx];
    }
    if (tid < 64) bias_s[tid] = rpb[tid];

    // ---- gather q (bilinear of Y_q): 64 px x 2 halves of 32 channels
    {
        int p2 = tid >> 1, qh = tid & 1;
        long pG = (long)pg0 + p2;
        int s = sIn + p2;
        int yI = s >> 8, xI = s & 255;
        float oy = g_off[(size_t)2 * NS + pG];
        float ox = g_off[(size_t)3 * NS + pG];
        float py = (float)yI + oy, px = (float)xI + ox;
        float y0f = floorf(py), x0f = floorf(px);
        int iy0 = (int)y0f, ix0 = (int)x0f;
        float ty = py - y0f, tx = px - x0f;
        float wg[4] = {(1.f - ty) * (1.f - tx), (1.f - ty) * tx,
                       ty * (1.f - tx), ty * tx};
        float acc[32];
#pragma unroll
        for (int i = 0; i < 32; i++) acc[i] = 0.f;
#pragma unroll
        for (int t = 0; t < 4; t++) {
            int iy = iy0 + (t >> 1), ix = ix0 + (t & 1);
            if (iy >= 0 && iy < 256 && ix >= 0 && ix < 256) {
                const float4* tp = (const float4*)(g_Yq +
                    ((((size_t)n << 16) | ((size_t)iy << 8) | (size_t)ix) * 64) + qh * 32);
                float w = wg[t];
#pragma unroll
                for (int i = 0; i < 8; i++) {
                    float4 v = tp[i];
                    acc[4 * i + 0] += w * v.x; acc[4 * i + 1] += w * v.y;
                    acc[4 * i + 2] += w * v.z; acc[4 * i + 3] += w * v.w;
                }
            }
        }
#pragma unroll
        for (int i = 0; i < 32; i++) qs[qh * 32 + i][p2] = acc[i];
    }
    __syncthreads();

    // ---- channel softmax per head: each thread handles 2 heads of one pixel
    {
        int p = tid >> 1, hb = (tid & 1) * 2;
#pragma unroll
        for (int hh = 0; hh < 2; hh++) {
            int h0 = hb + hh;
            float v[16];
#pragma unroll
            for (int i = 0; i < 16; i++) v[i] = qs[h0 * 16 + i][p];
            float m = v[0];
#pragma unroll
            for (int i = 1; i < 16; i++) m = fmaxf(m, v[i]);
            float sum = 0.f;
#pragma unroll
            for (int i = 0; i < 16; i++) { v[i] = __expf(v[i] - m); sum += v[i]; }
            float inv = 1.f / sum;
#pragma unroll
            for (int i = 0; i < 16; i++) qs[h0 * 16 + i][p] = v[i] * inv;
        }
    }
    __syncthreads();

    // ---- GEMM out = B · q_sm : 8 outputs x 4 pixels per thread
    int og = tid >> 4;   // 0..7
    int pg = tid & 15;   // 0..15
    ull acc[4][4];
#pragma unroll
    for (int j = 0; j < 4; j++)
#pragma unroll
        for (int i = 0; i < 4; i++) acc[j][i] = pk2(0.f, 0.f);

#pragma unroll 4
    for (int c = 0; c < 64; c++) {
        float2 x01 = *(const float2*)&qs[c][pg * 4];
        float2 x23 = *(const float2*)&qs[c][pg * 4 + 2];
        ull xd[4] = {pk2(x01.x, x01.x), pk2(x01.y, x01.y),
                     pk2(x23.x, x23.x), pk2(x23.y, x23.y)};
        float4 wa = *(const float4*)&bu[c][og * 8];
        float4 wb = *(const float4*)&bu[c][og * 8 + 4];
        ull wd[4] = {pk2(wa.x, wa.y), pk2(wa.z, wa.w),
                     pk2(wb.x, wb.y), pk2(wb.z, wb.w)};
#pragma unroll
        for (int j = 0; j < 4; j++)
#pragma unroll
            for (int i = 0; i < 4; i++)
                acc[j][i] = fma2(wd[j], xd[i], acc[j][i]);
    }

    // epilogue: channel-major out[N,C,H,W]; per output-channel a float4 over 4 pixels
#pragma unroll
    for (int j = 0; j < 4; j++) {
        int c0 = og * 8 + 2 * j;
        float l0, h0, l1, h1, l2, h2, l3, h3;
        upk2(acc[j][0], l0, h0); upk2(acc[j][1], l1, h1);
        upk2(acc[j][2], l2, h2); upk2(acc[j][3], l3, h3);
        float b0 = bias_s[c0], b1 = bias_s[c0 + 1];
        float* d0 = out + ((size_t)(n * 64 + c0)) * SS + sIn + pg * 4;
        float* d1 = out + ((size_t)(n * 64 + c0 + 1)) * SS + sIn + pg * 4;
        *(float4*)d0 = make_float4(l0 + b0, l1 + b0, l2 + b0, l3 + b0);
        *(float4*)d1 = make_float4(h0 + b1, h1 + b1, h2 + b1, h3 + b1);
    }
}

// ---------------- launch ----------------
extern "C" void kernel_launch(void* const* d_in, const int* in_sizes, int n_in,
                              void* d_out, int out_size) {
    const float* x   = (const float*)d_in[0];
    const float* kow = (const float*)d_in[1];
    const float* kob = (const float*)d_in[2];
    const float* kw  = (const float*)d_in[3];
    const float* qow = (const float*)d_in[4];
    const float* qob = (const float*)d_in[5];
    const float* qw  = (const float*)d_in[6];
    const float* vow = (const float*)d_in[7];
    const float* vob = (const float*)d_in[8];
    const float* vw  = (const float*)d_in[9];
    const float* rpw = (const float*)d_in[10];
    const float* rpb = (const float*)d_in[11];
    float* out = (float*)d_out;

    k_a<<<NS / 64, 128>>>(x, kow, kob, kw, qow, qob, qw, vow, vob, vw);
    k_b<<<1024, 256>>>();
    k_red2<<<544, 256>>>();
    k_fold2<<<64, 256>>>(rpw);
    k_c<<<NS / 64, 128>>>(rpb, out);
}

// round 7
// speedup vs baseline: 1.5421x; 1.2644x over previous
#include <cuda_runtime.h>
#include <cuda_bf16.h>
#include <cstdint>

#define NB 4
#define CC 64
#define SS 65536    // H*W
#define NS 262144   // NB*SS

// ---------------- scratch ----------------
__device__ float g_Yk[(size_t)NS * CC];   // pixel-major [N,S,C]
__device__ float g_Yq[(size_t)NS * CC];
__device__ float g_Yv[(size_t)NS * CC];
__device__ float g_off[(size_t)6 * NS];   // (ky,kx,qy,qx,vy,vx)
__device__ float g_ctxp[1024 * 1024];     // per-block ctx partials
__device__ float g_zp[1024 * 64];         // per-block Z partials
__device__ float g_ctx[NB * 1024];        // ctx [n][h][k][v]
__device__ float g_Z[NB * 64];
__device__ float g_B[NB * 64 * 64];       // folded matrix [n][o][kk]
__device__ uint32_t g_Wh[3 * 2048];       // bf16x2 split weights [proj][o][cpair]
__device__ uint32_t g_Wl[3 * 2048];

// ---------------- packed f32x2 helpers ----------------
typedef unsigned long long ull;
__device__ __forceinline__ ull pk2(float lo, float hi) {
    ull r; asm("mov.b64 %0, {%1, %2};" : "=l"(r) : "f"(lo), "f"(hi)); return r;
}
__device__ __forceinline__ void upk2(ull v, float& lo, float& hi) {
    asm("mov.b64 {%0, %1}, %2;" : "=f"(lo), "=f"(hi) : "l"(v));
}
__device__ __forceinline__ ull fma2(ull a, ull b, ull c) {
    ull d; asm("fma.rn.f32x2 %0, %1, %2, %3;" : "=l"(d) : "l"(a), "l"(b), "l"(c)); return d;
}

// ---------------- mma helpers ----------------
__device__ __forceinline__ uint32_t cvta_s(const void* p) {
    uint32_t a;
    asm("{ .reg .u64 t; cvta.to.shared.u64 t, %1; cvt.u32.u64 %0, t; }" : "=r"(a) : "l"(p));
    return a;
}
__device__ __forceinline__ void ldmx4(uint32_t* r, uint32_t a) {
    asm volatile("ldmatrix.sync.aligned.m8n8.x4.shared.b16 {%0,%1,%2,%3}, [%4];"
                 : "=r"(r[0]), "=r"(r[1]), "=r"(r[2]), "=r"(r[3]) : "r"(a));
}
__device__ __forceinline__ void ldmx2(uint32_t* r, uint32_t a) {
    asm volatile("ldmatrix.sync.aligned.m8n8.x2.shared.b16 {%0,%1}, [%2];"
                 : "=r"(r[0]), "=r"(r[1]) : "r"(a));
}
__device__ __forceinline__ void mma16816(float* d, const uint32_t* a, const uint32_t* b) {
    asm volatile("mma.sync.aligned.m16n8k16.row.col.f32.bf16.bf16.f32 "
                 "{%0,%1,%2,%3},{%4,%5,%6,%7},{%8,%9},{%0,%1,%2,%3};"
                 : "+f"(d[0]), "+f"(d[1]), "+f"(d[2]), "+f"(d[3])
                 : "r"(a[0]), "r"(a[1]), "r"(a[2]), "r"(a[3]), "r"(b[0]), "r"(b[1]));
}
__device__ __forceinline__ uint32_t bfsplit_hi(float v0, float v1, uint32_t& lo) {
    __nv_bfloat16 h0 = __float2bfloat16(v0), h1 = __float2bfloat16(v1);
    __nv_bfloat16 l0 = __float2bfloat16(v0 - __bfloat162float(h0));
    __nv_bfloat16 l1 = __float2bfloat16(v1 - __bfloat162float(h1));
    lo = (uint32_t)__bfloat16_as_ushort(l0) | ((uint32_t)__bfloat16_as_ushort(l1) << 16);
    return (uint32_t)__bfloat16_as_ushort(h0) | ((uint32_t)__bfloat16_as_ushort(h1) << 16);
}
// swizzled byte offset within a 64x128B tile
#define SWZ(row, cb) ((uint32_t)((row) * 128 + ((cb) ^ (((row) & 7) << 4))))

// =============== W prep: split weights to bf16 h/l (one-time tiny) ===============
__global__ __launch_bounds__(256) void k_wprep(const float* __restrict__ kw,
                                               const float* __restrict__ qw,
                                               const float* __restrict__ vw) {
    int idx = blockIdx.x * 256 + threadIdx.x;   // 6144
    int proj = idx >> 11, r = idx & 2047;
    const float* wp = proj == 0 ? kw : (proj == 1 ? qw : vw);
    int o = r >> 5, cp = r & 31;
    float v0 = wp[o * 64 + 2 * cp], v1 = wp[o * 64 + 2 * cp + 1];
    uint32_t lo, hi = bfsplit_hi(v0, v1, lo);
    g_Wh[idx] = hi; g_Wl[idx] = lo;
}

// =============== K_A: offsets + 3 projections via HMMA (split-bf16) ===========
// 128 threads (4 warps), 64-pixel tile; warp w owns rows w*16..w*16+15.
__global__ __launch_bounds__(128) void k_a(
    const float* __restrict__ x,
    const float* __restrict__ kow, const float* __restrict__ kob,
    const float* __restrict__ qow, const float* __restrict__ qob,
    const float* __restrict__ vow, const float* __restrict__ vob) {
    __shared__ __align__(16) unsigned char sm[32768 + 1600];
    // layout: Ah@0, Al@8192, Wh@16384, Wl@24576 (each 64 rows x 128B, SW-swizzled)
    float* owf = (float*)(sm + 32768);          // [6][64]
    float* obf = (float*)(sm + 32768 + 1536);   // [6]

    int tid = threadIdx.x;
    int lane = tid & 31, wid = tid >> 5;
    uint32_t base = cvta_s(sm);

    int pg0 = blockIdx.x * 64;
    int n   = pg0 >> 16;
    int sIn = pg0 & 65535;

    // ---- stage x (split bf16, swizzled)
    const float* xb = x + (size_t)n * CC * SS + sIn;
#pragma unroll
    for (int it = 0; it < 16; it++) {
        int idx = tid + 128 * it;               // 2048 c-pairs
        int cp = idx >> 6, p = idx & 63;
        float v0 = xb[(size_t)(2 * cp) * SS + p];
        float v1 = xb[(size_t)(2 * cp + 1) * SS + p];
        uint32_t lo, hi = bfsplit_hi(v0, v1, lo);
        uint32_t off = SWZ(p, cp * 4);
        *(uint32_t*)(sm + off) = hi;
        *(uint32_t*)(sm + 8192 + off) = lo;
    }
    if (tid < 128) { owf[tid] = kow[tid]; owf[128 + tid] = qow[tid]; owf[256 + tid] = vow[tid]; }
    if (tid < 2) { obf[tid] = kob[tid]; obf[2 + tid] = qob[tid]; obf[4 + tid] = vob[tid]; }
    __syncthreads();

    // ---- offsets (reconstruct x = xh + xl)
    {
        int p = tid >> 1, half = tid & 1;
        float od[6] = {0.f, 0.f, 0.f, 0.f, 0.f, 0.f};
#pragma unroll
        for (int i = 0; i < 16; i++) {
            uint32_t off = SWZ(p, half * 64 + 4 * i);
            uint32_t hh = *(const uint32_t*)(sm + off);
            uint32_t ll = *(const uint32_t*)(sm + 8192 + off);
            __nv_bfloat162 h2 = *reinterpret_cast<__nv_bfloat162*>(&hh);
            __nv_bfloat162 l2 = *reinterpret_cast<__nv_bfloat162*>(&ll);
            float x0 = __low2float(h2) + __low2float(l2);
            float x1 = __high2float(h2) + __high2float(l2);
            int c = half * 32 + 2 * i;
#pragma unroll
            for (int d = 0; d < 6; d++)
                od[d] += x0 * owf[d * 64 + c] + x1 * owf[d * 64 + c + 1];
        }
#pragma unroll
        for (int d = 0; d < 6; d++) od[d] += __shfl_xor_sync(0xffffffffu, od[d], 1);
        if (half == 0) {
#pragma unroll
            for (int d = 0; d < 6; d++)
                g_off[(size_t)d * NS + pg0 + p] = od[d] + obf[d];
        }
    }

    // ---- load A fragments (held across all 3 projections)
    uint32_t ah[4][4], alf[4][4];
    {
        int p0 = wid * 16;
        int arow = p0 + (lane & 15);
#pragma unroll
        for (int k = 0; k < 4; k++) {
            uint32_t cb = k * 32 + (lane >> 4) * 16;
            uint32_t off = SWZ(arow, cb);
            ldmx4(ah[k], base + off);
            ldmx4(alf[k], base + 8192 + off);
        }
    }

    float* yd3[3] = {g_Yk, g_Yq, g_Yv};
    for (int pr = 0; pr < 3; pr++) {
        __syncthreads();
        // stage W (pre-split)
        const uint32_t* wh = g_Wh + pr * 2048;
        const uint32_t* wl = g_Wl + pr * 2048;
#pragma unroll
        for (int it = 0; it < 16; it++) {
            int idx = tid + 128 * it;
            int o = idx >> 5, cp = idx & 31;
            uint32_t off = SWZ(o, cp * 4);
            *(uint32_t*)(sm + 16384 + off) = wh[idx];
            *(uint32_t*)(sm + 24576 + off) = wl[idx];
        }
        __syncthreads();

        float* yb = yd3[pr] + (size_t)pg0 * 64;
        int p0 = wid * 16;
#pragma unroll 2
        for (int nt = 0; nt < 8; nt++) {
            float d[4] = {0.f, 0.f, 0.f, 0.f};
            int orow = nt * 8 + (lane & 7);
#pragma unroll
            for (int k = 0; k < 4; k++) {
                uint32_t cb = k * 32 + ((lane >> 3) & 1) * 16;
                uint32_t off = SWZ(orow, cb);
                uint32_t bh[2], bl[2];
                ldmx2(bh, base + 16384 + off);
                mma16816(d, ah[k], bh);
                mma16816(d, alf[k], bh);
                ldmx2(bl, base + 24576 + off);
                mma16816(d, ah[k], bl);
            }
            int r0 = p0 + (lane >> 2);
            int col = nt * 8 + 2 * (lane & 3);
            *(float2*)(yb + (size_t)r0 * 64 + col) = make_float2(d[0], d[1]);
            *(float2*)(yb + (size_t)(r0 + 8) * 64 + col) = make_float2(d[2], d[3]);
        }
    }
}

// =============== K_B: gather K,V + exp + context/Z partials ===============
// grid 1024; 4 tiles of 64 px per block.
__global__ __launch_bounds__(256) void k_b() {
    __shared__ float Ke[64][68];
    __shared__ float Vs[64][68];

    int tid = threadIdx.x;
    int h = tid >> 6, k = (tid >> 2) & 15, vg = tid & 3;
    int p4 = tid >> 2, qd = tid & 3;

    float a0 = 0.f, a1 = 0.f, a2 = 0.f, a3 = 0.f, z = 0.f;

    for (int tile = 0; tile < 4; tile++) {
        int pg0 = (blockIdx.x * 4 + tile) * 64;
        int n   = pg0 >> 16;
        int sIn = pg0 & 65535;
        long pG = (long)pg0 + p4;
        int s   = sIn + p4;
        int yI  = s >> 8, xI = s & 255;

#pragma unroll
        for (int tv = 0; tv < 2; tv++) {
            const float* Ysrc = tv ? g_Yv : g_Yk;
            int dB = tv ? 4 : 0;
            float oy = g_off[(size_t)dB * NS + pG];
            float ox = g_off[(size_t)(dB + 1) * NS + pG];
            float py = (float)yI + oy, px = (float)xI + ox;
            float y0f = floorf(py), x0f = floorf(px);
            int iy0 = (int)y0f, ix0 = (int)x0f;
            float ty = py - y0f, tx = px - x0f;
            float wg[4] = {(1.f - ty) * (1.f - tx), (1.f - ty) * tx,
                           ty * (1.f - tx), ty * tx};
            float4 acc[4];
#pragma unroll
            for (int i = 0; i < 4; i++) acc[i] = make_float4(0.f, 0.f, 0.f, 0.f);
#pragma unroll
            for (int t = 0; t < 4; t++) {
                int iy = iy0 + (t >> 1), ix = ix0 + (t & 1);
                if (iy >= 0 && iy < 256 && ix >= 0 && ix < 256) {
                    const float4* tp = (const float4*)(Ysrc +
                        ((((size_t)n << 16) | ((size_t)iy << 8) | (size_t)ix) * 64) + qd * 16);
                    float w = wg[t];
#pragma unroll
                    for (int i = 0; i < 4; i++) {
                        float4 v = tp[i];
                        acc[i].x += w * v.x; acc[i].y += w * v.y;
                        acc[i].z += w * v.z; acc[i].w += w * v.w;
                    }
                }
            }
            if (tv == 0) {
#pragma unroll
                for (int i = 0; i < 4; i++) {
                    acc[i].x = __expf(acc[i].x); acc[i].y = __expf(acc[i].y);
                    acc[i].z = __expf(acc[i].z); acc[i].w = __expf(acc[i].w);
                    *(float4*)&Ke[p4][qd * 16 + 4 * i] = acc[i];
                }
            } else {
#pragma unroll
                for (int i = 0; i < 4; i++)
                    *(float4*)&Vs[p4][qd * 16 + 4 * i] = acc[i];
            }
        }
        __syncthreads();

#pragma unroll 8
        for (int p = 0; p < 64; p++) {
            float kv = Ke[p][h * 16 + k];
            float4 v4 = *(const float4*)&Vs[p][h * 16 + vg * 4];
            a0 += kv * v4.x; a1 += kv * v4.y; a2 += kv * v4.z; a3 += kv * v4.w;
            z += kv;
        }
        __syncthreads();
    }

    size_t base = (size_t)blockIdx.x * 1024 + h * 256 + k * 16 + vg * 4;
    g_ctxp[base + 0] = a0; g_ctxp[base + 1] = a1;
    g_ctxp[base + 2] = a2; g_ctxp[base + 3] = a3;
    if (vg == 0) g_zp[blockIdx.x * 64 + h * 16 + k] = z;
}

// =============== reduce partials: warp per row ===============
__global__ __launch_bounds__(256) void k_red2() {
    int wid = threadIdx.x >> 5, lid = threadIdx.x & 31;
    if (blockIdx.x < 512) {
        int row = blockIdx.x * 8 + wid;            // 4096 ctx rows
        int n = row >> 10, idx = row & 1023;
        float v = 0.f;
#pragma unroll
        for (int j = 0; j < 8; j++)
            v += g_ctxp[((size_t)(n * 256 + j * 32 + lid)) * 1024 + idx];
#pragma unroll
        for (int o = 16; o > 0; o >>= 1) v += __shfl_xor_sync(0xffffffffu, v, o);
        if (lid == 0) g_ctx[row] = v;
    } else {
        int zrow = (blockIdx.x - 512) * 8 + wid;   // 256 z rows
        int n = zrow >> 6, kk = zrow & 63;
        float v = 0.f;
#pragma unroll
        for (int j = 0; j < 8; j++)
            v += g_zp[(n * 256 + j * 32 + lid) * 64 + kk];
#pragma unroll
        for (int o = 16; o > 0; o >>= 1) v += __shfl_xor_sync(0xffffffffu, v, o);
        if (lid == 0) g_Z[zrow] = v;
    }
}

// =============== fold: B[n][o][kk] ===============
__global__ __launch_bounds__(256) void k_fold2(const float* __restrict__ rpw) {
    int idx = blockIdx.x * 256 + threadIdx.x;    // 16384 outputs
    int n = idx >> 12, o = (idx >> 6) & 63, kk = idx & 63;
    int h = kk >> 4, k = kk & 15;
    const float* cx = g_ctx + n * 1024 + h * 256 + k * 16;
    const float* wr = rpw + o * 64 + h * 16;
    float a = 0.f;
#pragma unroll
    for (int v = 0; v < 16; v++) a += wr[v] * cx[v];
    g_B[n * 4096 + (o << 6) + kk] = a / g_Z[n * 64 + kk];
}

// =============== K_C: gather Q + channel softmax + B-GEMM + bias ===============
// 128 threads, 64-pixel tile. Each thread: 8 output channels x 4 pixels.
__global__ __launch_bounds__(128) void k_c(const float* __restrict__ rpb,
                                           float* __restrict__ out) {
    __shared__ float qs[64][68];   // [kk][p]
    __shared__ float bu[64][68];   // B transposed [kk][o]
    __shared__ float bias_s[64];

    int tid = threadIdx.x;
    int pg0 = blockIdx.x * 64;
    int n   = pg0 >> 16;
    int sIn = pg0 & 65535;

    const float* Bn = g_B + (size_t)n * 4096;
#pragma unroll
    for (int it = 0; it < 32; it++) {
        int idx = tid + 128 * it;
        int o = idx >> 6, kk = idx & 63;
        bu[kk][o] = Bn[idx];
    }
    if (tid < 64) bias_s[tid] = rpb[tid];

    // ---- gather q (bilinear of Y_q): 64 px x 2 halves of 32 channels
    {
        int p2 = tid >> 1, qh = tid & 1;
        long pG = (long)pg0 + p2;
        int s = sIn + p2;
        int yI = s >> 8, xI = s & 255;
        float oy = g_off[(size_t)2 * NS + pG];
        float ox = g_off[(size_t)3 * NS + pG];
        float py = (float)yI + oy, px = (float)xI + ox;
        float y0f = floorf(py), x0f = floorf(px);
        int iy0 = (int)y0f, ix0 = (int)x0f;
        float ty = py - y0f, tx = px - x0f;
        float wg[4] = {(1.f - ty) * (1.f - tx), (1.f - ty) * tx,
                       ty * (1.f - tx), ty * tx};
        float acc[32];
#pragma unroll
        for (int i = 0; i < 32; i++) acc[i] = 0.f;
#pragma unroll
        for (int t = 0; t < 4; t++) {
            int iy = iy0 + (t >> 1), ix = ix0 + (t & 1);
            if (iy >= 0 && iy < 256 && ix >= 0 && ix < 256) {
                const float4* tp = (const float4*)(g_Yq +
                    ((((size_t)n << 16) | ((size_t)iy << 8) | (size_t)ix) * 64) + qh * 32);
                float w = wg[t];
#pragma unroll
                for (int i = 0; i < 8; i++) {
                    float4 v = tp[i];
                    acc[4 * i + 0] += w * v.x; acc[4 * i + 1] += w * v.y;
                    acc[4 * i + 2] += w * v.z; acc[4 * i + 3] += w * v.w;
                }
            }
        }
#pragma unroll
        for (int i = 0; i < 32; i++) qs[qh * 32 + i][p2] = acc[i];
    }
    __syncthreads();

    // ---- channel softmax per head: each thread handles 2 heads of one pixel
    {
        int p = tid >> 1, hb = (tid & 1) * 2;
#pragma unroll
        for (int hh = 0; hh < 2; hh++) {
            int h0 = hb + hh;
            float v[16];
#pragma unroll
            for (int i = 0; i < 16; i++) v[i] = qs[h0 * 16 + i][p];
            float m = v[0];
#pragma unroll
            for (int i = 1; i < 16; i++) m = fmaxf(m, v[i]);
            float sum = 0.f;
#pragma unroll
            for (int i = 0; i < 16; i++) { v[i] = __expf(v[i] - m); sum += v[i]; }
            float inv = 1.f / sum;
#pragma unroll
            for (int i = 0; i < 16; i++) qs[h0 * 16 + i][p] = v[i] * inv;
        }
    }
    __syncthreads();

    // ---- GEMM out = B · q_sm : 8 outputs x 4 pixels per thread
    int og = tid >> 4;   // 0..7
    int pg = tid & 15;   // 0..15
    ull acc[4][4];
#pragma unroll
    for (int j = 0; j < 4; j++)
#pragma unroll
        for (int i = 0; i < 4; i++) acc[j][i] = pk2(0.f, 0.f);

#pragma unroll 4
    for (int c = 0; c < 64; c++) {
        float2 x01 = *(const float2*)&qs[c][pg * 4];
        float2 x23 = *(const float2*)&qs[c][pg * 4 + 2];
        ull xd[4] = {pk2(x01.x, x01.x), pk2(x01.y, x01.y),
                     pk2(x23.x, x23.x), pk2(x23.y, x23.y)};
        float4 wa = *(const float4*)&bu[c][og * 8];
        float4 wb = *(const float4*)&bu[c][og * 8 + 4];
        ull wd[4] = {pk2(wa.x, wa.y), pk2(wa.z, wa.w),
                     pk2(wb.x, wb.y), pk2(wb.z, wb.w)};
#pragma unroll
        for (int j = 0; j < 4; j++)
#pragma unroll
            for (int i = 0; i < 4; i++)
                acc[j][i] = fma2(wd[j], xd[i], acc[j][i]);
    }

    // epilogue: channel-major out[N,C,H,W]
#pragma unroll
    for (int j = 0; j < 4; j++) {
        int c0 = og * 8 + 2 * j;
        float l0, h0, l1, h1, l2, h2, l3, h3;
        upk2(acc[j][0], l0, h0); upk2(acc[j][1], l1, h1);
        upk2(acc[j][2], l2, h2); upk2(acc[j][3], l3, h3);
        float b0 = bias_s[c0], b1 = bias_s[c0 + 1];
        float* d0 = out + ((size_t)(n * 64 + c0)) * SS + sIn + pg * 4;
        float* d1 = out + ((size_t)(n * 64 + c0 + 1)) * SS + sIn + pg * 4;
        *(float4*)d0 = make_float4(l0 + b0, l1 + b0, l2 + b0, l3 + b0);
        *(float4*)d1 = make_float4(h0 + b1, h1 + b1, h2 + b1, h3 + b1);
    }
}

// ---------------- launch ----------------
extern "C" void kernel_launch(void* const* d_in, const int* in_sizes, int n_in,
                              void* d_out, int out_size) {
    const float* x   = (const float*)d_in[0];
    const float* kow = (const float*)d_in[1];
    const float* kob = (const float*)d_in[2];
    const float* kw  = (const float*)d_in[3];
    const float* qow = (const float*)d_in[4];
    const float* qob = (const float*)d_in[5];
    const float* qw  = (const float*)d_in[6];
    const float* vow = (const float*)d_in[7];
    const float* vob = (const float*)d_in[8];
    const float* vw  = (const float*)d_in[9];
    const float* rpw = (const float*)d_in[10];
    const float* rpb = (const float*)d_in[11];
    float* out = (float*)d_out;

    k_wprep<<<24, 256>>>(kw, qw, vw);
    k_a<<<NS / 64, 128>>>(x, kow, kob, qow, qob, vow, vob);
    k_b<<<1024, 256>>>();
    k_red2<<<544, 256>>>();
    k_fold2<<<64, 256>>>(rpw);
    k_c<<<NS / 64, 128>>>(rpb, out);
}

// round 8
// speedup vs baseline: 1.5940x; 1.0337x over previous
#include <cuda_runtime.h>
#include <cuda_bf16.h>
#include <cstdint>

#define NB 4
#define CC 64
#define SS 65536    // H*W
#define NS 262144   // NB*SS

// ---------------- scratch ----------------
__device__ float g_Yk[(size_t)NS * CC];   // pixel-major [N,S,C]
__device__ float g_Yq[(size_t)NS * CC];
__device__ float g_Yv[(size_t)NS * CC];
__device__ float g_off[(size_t)6 * NS];   // (ky,kx,qy,qx,vy,vx)
__device__ float g_ctxp[1024 * 1024];     // per-block ctx partials
__device__ float g_zp[1024 * 64];         // per-block Z partials
__device__ float g_ctx[NB * 1024];        // ctx [n][h][k][v]
__device__ float g_Z[NB * 64];
__device__ uint32_t g_Wh[3 * 2048];       // bf16x2 split weights [proj][o][cpair]
__device__ uint32_t g_Wl[3 * 2048];
__device__ uint32_t g_Bh[NB * 2048];      // bf16x2 split folded matrix [n][o][kkpair]
__device__ uint32_t g_Bl[NB * 2048];

// ---------------- mma helpers ----------------
__device__ __forceinline__ uint32_t cvta_s(const void* p) {
    uint32_t a;
    asm("{ .reg .u64 t; cvta.to.shared.u64 t, %1; cvt.u32.u64 %0, t; }" : "=r"(a) : "l"(p));
    return a;
}
__device__ __forceinline__ void ldmx4(uint32_t* r, uint32_t a) {
    asm volatile("ldmatrix.sync.aligned.m8n8.x4.shared.b16 {%0,%1,%2,%3}, [%4];"
                 : "=r"(r[0]), "=r"(r[1]), "=r"(r[2]), "=r"(r[3]) : "r"(a));
}
__device__ __forceinline__ void ldmx2(uint32_t* r, uint32_t a) {
    asm volatile("ldmatrix.sync.aligned.m8n8.x2.shared.b16 {%0,%1}, [%2];"
                 : "=r"(r[0]), "=r"(r[1]) : "r"(a));
}
__device__ __forceinline__ void mma16816(float* d, const uint32_t* a, const uint32_t* b) {
    asm volatile("mma.sync.aligned.m16n8k16.row.col.f32.bf16.bf16.f32 "
                 "{%0,%1,%2,%3},{%4,%5,%6,%7},{%8,%9},{%0,%1,%2,%3};"
                 : "+f"(d[0]), "+f"(d[1]), "+f"(d[2]), "+f"(d[3])
                 : "r"(a[0]), "r"(a[1]), "r"(a[2]), "r"(a[3]), "r"(b[0]), "r"(b[1]));
}
__device__ __forceinline__ uint32_t bfsplit_hi(float v0, float v1, uint32_t& lo) {
    __nv_bfloat16 h0 = __float2bfloat16(v0), h1 = __float2bfloat16(v1);
    __nv_bfloat16 l0 = __float2bfloat16(v0 - __bfloat162float(h0));
    __nv_bfloat16 l1 = __float2bfloat16(v1 - __bfloat162float(h1));
    lo = (uint32_t)__bfloat16_as_ushort(l0) | ((uint32_t)__bfloat16_as_ushort(l1) << 16);
    return (uint32_t)__bfloat16_as_ushort(h0) | ((uint32_t)__bfloat16_as_ushort(h1) << 16);
}
// swizzled byte offset within a 64x128B tile
#define SWZ(row, cb) ((uint32_t)((row) * 128 + ((cb) ^ (((row) & 7) << 4))))

// =============== W prep: split weights to bf16 h/l ===============
__global__ __launch_bounds__(256) void k_wprep(const float* __restrict__ kw,
                                               const float* __restrict__ qw,
                                               const float* __restrict__ vw) {
    int idx = blockIdx.x * 256 + threadIdx.x;   // 6144
    int proj = idx >> 11, r = idx & 2047;
    const float* wp = proj == 0 ? kw : (proj == 1 ? qw : vw);
    int o = r >> 5, cp = r & 31;
    float v0 = wp[o * 64 + 2 * cp], v1 = wp[o * 64 + 2 * cp + 1];
    uint32_t lo, hi = bfsplit_hi(v0, v1, lo);
    g_Wh[idx] = hi; g_Wl[idx] = lo;
}

// =============== K_A: offsets + 3 projections via HMMA (split-bf16) ===========
__global__ __launch_bounds__(128) void k_a(
    const float* __restrict__ x,
    const float* __restrict__ kow, const float* __restrict__ kob,
    const float* __restrict__ qow, const float* __restrict__ qob,
    const float* __restrict__ vow, const float* __restrict__ vob) {
    __shared__ __align__(16) unsigned char sm[32768 + 1600];
    float* owf = (float*)(sm + 32768);          // [6][64]
    float* obf = (float*)(sm + 32768 + 1536);   // [6]

    int tid = threadIdx.x;
    int lane = tid & 31, wid = tid >> 5;
    uint32_t base = cvta_s(sm);

    int pg0 = blockIdx.x * 64;
    int n   = pg0 >> 16;
    int sIn = pg0 & 65535;

    const float* xb = x + (size_t)n * CC * SS + sIn;
#pragma unroll
    for (int it = 0; it < 16; it++) {
        int idx = tid + 128 * it;               // 2048 c-pairs
        int cp = idx >> 6, p = idx & 63;
        float v0 = xb[(size_t)(2 * cp) * SS + p];
        float v1 = xb[(size_t)(2 * cp + 1) * SS + p];
        uint32_t lo, hi = bfsplit_hi(v0, v1, lo);
        uint32_t off = SWZ(p, cp * 4);
        *(uint32_t*)(sm + off) = hi;
        *(uint32_t*)(sm + 8192 + off) = lo;
    }
    if (tid < 128) { owf[tid] = kow[tid]; owf[128 + tid] = qow[tid]; owf[256 + tid] = vow[tid]; }
    if (tid < 2) { obf[tid] = kob[tid]; obf[2 + tid] = qob[tid]; obf[4 + tid] = vob[tid]; }
    __syncthreads();

    // ---- offsets (reconstruct x = xh + xl)
    {
        int p = tid >> 1, half = tid & 1;
        float od[6] = {0.f, 0.f, 0.f, 0.f, 0.f, 0.f};
#pragma unroll
        for (int i = 0; i < 16; i++) {
            uint32_t off = SWZ(p, half * 64 + 4 * i);
            uint32_t hh = *(const uint32_t*)(sm + off);
            uint32_t ll = *(const uint32_t*)(sm + 8192 + off);
            __nv_bfloat162 h2 = *reinterpret_cast<__nv_bfloat162*>(&hh);
            __nv_bfloat162 l2 = *reinterpret_cast<__nv_bfloat162*>(&ll);
            float x0 = __low2float(h2) + __low2float(l2);
            float x1 = __high2float(h2) + __high2float(l2);
            int c = half * 32 + 2 * i;
#pragma unroll
            for (int d = 0; d < 6; d++)
                od[d] += x0 * owf[d * 64 + c] + x1 * owf[d * 64 + c + 1];
        }
#pragma unroll
        for (int d = 0; d < 6; d++) od[d] += __shfl_xor_sync(0xffffffffu, od[d], 1);
        if (half == 0) {
#pragma unroll
            for (int d = 0; d < 6; d++)
                g_off[(size_t)d * NS + pg0 + p] = od[d] + obf[d];
        }
    }

    // ---- A fragments held across all projections
    uint32_t ah[4][4], alf[4][4];
    {
        int arow = wid * 16 + (lane & 15);
#pragma unroll
        for (int k = 0; k < 4; k++) {
            uint32_t cb = k * 32 + (lane >> 4) * 16;
            uint32_t off = SWZ(arow, cb);
            ldmx4(ah[k], base + off);
            ldmx4(alf[k], base + 8192 + off);
        }
    }

    float* yd3[3] = {g_Yk, g_Yq, g_Yv};
    for (int pr = 0; pr < 3; pr++) {
        __syncthreads();
        const uint32_t* wh = g_Wh + pr * 2048;
        const uint32_t* wl = g_Wl + pr * 2048;
#pragma unroll
        for (int it = 0; it < 16; it++) {
            int idx = tid + 128 * it;
            int o = idx >> 5, cp = idx & 31;
            uint32_t off = SWZ(o, cp * 4);
            *(uint32_t*)(sm + 16384 + off) = wh[idx];
            *(uint32_t*)(sm + 24576 + off) = wl[idx];
        }
        __syncthreads();

        float* yb = yd3[pr] + (size_t)pg0 * 64;
        int p0 = wid * 16;
#pragma unroll 2
        for (int nt = 0; nt < 8; nt++) {
            float d[4] = {0.f, 0.f, 0.f, 0.f};
            int orow = nt * 8 + (lane & 7);
#pragma unroll
            for (int k = 0; k < 4; k++) {
                uint32_t cb = k * 32 + ((lane >> 3) & 1) * 16;
                uint32_t off = SWZ(orow, cb);
                uint32_t bh[2], bl[2];
                ldmx2(bh, base + 16384 + off);
                mma16816(d, ah[k], bh);
                mma16816(d, alf[k], bh);
                ldmx2(bl, base + 24576 + off);
                mma16816(d, ah[k], bl);
            }
            int r0 = p0 + (lane >> 2);
            int col = nt * 8 + 2 * (lane & 3);
            *(float2*)(yb + (size_t)r0 * 64 + col) = make_float2(d[0], d[1]);
            *(float2*)(yb + (size_t)(r0 + 8) * 64 + col) = make_float2(d[2], d[3]);
        }
    }
}

// =============== K_B: gather K,V + exp + context/Z partials ===============
__global__ __launch_bounds__(256) void k_b() {
    __shared__ float Ke[64][68];
    __shared__ float Vs[64][68];

    int tid = threadIdx.x;
    int h = tid >> 6, k = (tid >> 2) & 15, vg = tid & 3;
    int p4 = tid >> 2, qd = tid & 3;

    float a0 = 0.f, a1 = 0.f, a2 = 0.f, a3 = 0.f, z = 0.f;

    for (int tile = 0; tile < 4; tile++) {
        int pg0 = (blockIdx.x * 4 + tile) * 64;
        int n   = pg0 >> 16;
        int sIn = pg0 & 65535;
        long pG = (long)pg0 + p4;
        int s   = sIn + p4;
        int yI  = s >> 8, xI = s & 255;

#pragma unroll
        for (int tv = 0; tv < 2; tv++) {
            const float* Ysrc = tv ? g_Yv : g_Yk;
            int dB = tv ? 4 : 0;
            float oy = g_off[(size_t)dB * NS + pG];
            float ox = g_off[(size_t)(dB + 1) * NS + pG];
            float py = (float)yI + oy, px = (float)xI + ox;
            float y0f = floorf(py), x0f = floorf(px);
            int iy0 = (int)y0f, ix0 = (int)x0f;
            float ty = py - y0f, tx = px - x0f;
            float wg[4] = {(1.f - ty) * (1.f - tx), (1.f - ty) * tx,
                           ty * (1.f - tx), ty * tx};
            float4 acc[4];
#pragma unroll
            for (int i = 0; i < 4; i++) acc[i] = make_float4(0.f, 0.f, 0.f, 0.f);
#pragma unroll
            for (int t = 0; t < 4; t++) {
                int iy = iy0 + (t >> 1), ix = ix0 + (t & 1);
                if (iy >= 0 && iy < 256 && ix >= 0 && ix < 256) {
                    const float4* tp = (const float4*)(Ysrc +
                        ((((size_t)n << 16) | ((size_t)iy << 8) | (size_t)ix) * 64) + qd * 16);
                    float w = wg[t];
#pragma unroll
                    for (int i = 0; i < 4; i++) {
                        float4 v = tp[i];
                        acc[i].x += w * v.x; acc[i].y += w * v.y;
                        acc[i].z += w * v.z; acc[i].w += w * v.w;
                    }
                }
            }
            if (tv == 0) {
#pragma unroll
                for (int i = 0; i < 4; i++) {
                    acc[i].x = __expf(acc[i].x); acc[i].y = __expf(acc[i].y);
                    acc[i].z = __expf(acc[i].z); acc[i].w = __expf(acc[i].w);
                    *(float4*)&Ke[p4][qd * 16 + 4 * i] = acc[i];
                }
            } else {
#pragma unroll
                for (int i = 0; i < 4; i++)
                    *(float4*)&Vs[p4][qd * 16 + 4 * i] = acc[i];
            }
        }
        __syncthreads();

#pragma unroll 8
        for (int p = 0; p < 64; p++) {
            float kv = Ke[p][h * 16 + k];
            float4 v4 = *(const float4*)&Vs[p][h * 16 + vg * 4];
            a0 += kv * v4.x; a1 += kv * v4.y; a2 += kv * v4.z; a3 += kv * v4.w;
            z += kv;
        }
        __syncthreads();
    }

    size_t base = (size_t)blockIdx.x * 1024 + h * 256 + k * 16 + vg * 4;
    g_ctxp[base + 0] = a0; g_ctxp[base + 1] = a1;
    g_ctxp[base + 2] = a2; g_ctxp[base + 3] = a3;
    if (vg == 0) g_zp[blockIdx.x * 64 + h * 16 + k] = z;
}

// =============== reduce partials: warp per row ===============
__global__ __launch_bounds__(256) void k_red2() {
    int wid = threadIdx.x >> 5, lid = threadIdx.x & 31;
    if (blockIdx.x < 512) {
        int row = blockIdx.x * 8 + wid;            // 4096 ctx rows
        int n = row >> 10, idx = row & 1023;
        float v = 0.f;
#pragma unroll
        for (int j = 0; j < 8; j++)
            v += g_ctxp[((size_t)(n * 256 + j * 32 + lid)) * 1024 + idx];
#pragma unroll
        for (int o = 16; o > 0; o >>= 1) v += __shfl_xor_sync(0xffffffffu, v, o);
        if (lid == 0) g_ctx[row] = v;
    } else {
        int zrow = (blockIdx.x - 512) * 8 + wid;   // 256 z rows
        int n = zrow >> 6, kk = zrow & 63;
        float v = 0.f;
#pragma unroll
        for (int j = 0; j < 8; j++)
            v += g_zp[(n * 256 + j * 32 + lid) * 64 + kk];
#pragma unroll
        for (int o = 16; o > 0; o >>= 1) v += __shfl_xor_sync(0xffffffffu, v, o);
        if (lid == 0) g_Z[zrow] = v;
    }
}

// =============== fold: B[n][o][kk] -> split bf16 h/l pairs ===============
__global__ __launch_bounds__(256) void k_fold2(const float* __restrict__ rpw) {
    int idx = blockIdx.x * 256 + threadIdx.x;    // 8192 pairs
    int n = idx >> 11, r = idx & 2047;
    int o = r >> 5, cp = r & 31;
    float b2[2];
#pragma unroll
    for (int e = 0; e < 2; e++) {
        int kk = 2 * cp + e;
        int h = kk >> 4, k = kk & 15;
        const float* cx = g_ctx + n * 1024 + h * 256 + k * 16;
        const float* wr = rpw + o * 64 + h * 16;
        float a = 0.f;
#pragma unroll
        for (int v = 0; v < 16; v++) a += wr[v] * cx[v];
        b2[e] = a / g_Z[n * 64 + kk];
    }
    uint32_t lo, hi = bfsplit_hi(b2[0], b2[1], lo);
    g_Bh[idx] = hi; g_Bl[idx] = lo;
}

// =============== K_C: gather Q + reg softmax + HMMA B-GEMM + bias ===========
// 128 threads, 64-pixel tile. Tiles: Qh@0 Ql@8192 Bh@16384 Bl@24576.
__global__ __launch_bounds__(128) void k_c(const float* __restrict__ rpb,
                                           float* __restrict__ out) {
    __shared__ __align__(16) unsigned char sm[32768 + 256];
    float* bias_s = (float*)(sm + 32768);

    int tid = threadIdx.x;
    int lane = tid & 31, wid = tid >> 5;
    uint32_t base = cvta_s(sm);

    int pg0 = blockIdx.x * 64;
    int n   = pg0 >> 16;
    int sIn = pg0 & 65535;

    // stage split B-matrix tiles
    const uint32_t* bh = g_Bh + n * 2048;
    const uint32_t* bl = g_Bl + n * 2048;
#pragma unroll
    for (int it = 0; it < 16; it++) {
        int idx = tid + 128 * it;
        int o = idx >> 5, cp = idx & 31;
        uint32_t off = SWZ(o, cp * 4);
        *(uint32_t*)(sm + 16384 + off) = bh[idx];
        *(uint32_t*)(sm + 24576 + off) = bl[idx];
    }
    if (tid < 64) bias_s[tid] = rpb[tid];

    // ---- gather q + in-register softmax (2 heads per thread) + split store
    {
        int p2 = tid >> 1, qh = tid & 1;
        long pG = (long)pg0 + p2;
        int s = sIn + p2;
        int yI = s >> 8, xI = s & 255;
        float oy = g_off[(size_t)2 * NS + pG];
        float ox = g_off[(size_t)3 * NS + pG];
        float py = (float)yI + oy, px = (float)xI + ox;
        float y0f = floorf(py), x0f = floorf(px);
        int iy0 = (int)y0f, ix0 = (int)x0f;
        float ty = py - y0f, tx = px - x0f;
        float wg[4] = {(1.f - ty) * (1.f - tx), (1.f - ty) * tx,
                       ty * (1.f - tx), ty * tx};
        float acc[32];
#pragma unroll
        for (int i = 0; i < 32; i++) acc[i] = 0.f;
#pragma unroll
        for (int t = 0; t < 4; t++) {
            int iy = iy0 + (t >> 1), ix = ix0 + (t & 1);
            if (iy >= 0 && iy < 256 && ix >= 0 && ix < 256) {
                const float4* tp = (const float4*)(g_Yq +
                    ((((size_t)n << 16) | ((size_t)iy << 8) | (size_t)ix) * 64) + qh * 32);
                float w = wg[t];
#pragma unroll
                for (int i = 0; i < 8; i++) {
                    float4 v = tp[i];
                    acc[4 * i + 0] += w * v.x; acc[4 * i + 1] += w * v.y;
                    acc[4 * i + 2] += w * v.z; acc[4 * i + 3] += w * v.w;
                }
            }
        }
        // softmax per head, entirely in registers
#pragma unroll
        for (int hh = 0; hh < 2; hh++) {
            float* v = acc + hh * 16;
            float m = v[0];
#pragma unroll
            for (int i = 1; i < 16; i++) m = fmaxf(m, v[i]);
            float sum = 0.f;
#pragma unroll
            for (int i = 0; i < 16; i++) { v[i] = __expf(v[i] - m); sum += v[i]; }
            float inv = 1.f / sum;
#pragma unroll
            for (int i = 0; i < 16; i++) v[i] *= inv;
        }
        // split + swizzled store: row = pixel p2, cpairs qh*16..qh*16+15
#pragma unroll
        for (int i = 0; i < 16; i++) {
            uint32_t lo, hi = bfsplit_hi(acc[2 * i], acc[2 * i + 1], lo);
            uint32_t off = SWZ(p2, (qh * 16 + i) * 4);
            *(uint32_t*)(sm + off) = hi;
            *(uint32_t*)(sm + 8192 + off) = lo;
        }
    }
    __syncthreads();

    // ---- A frags = B-matrix rows (channels); warp owns channels wid*16..+15
    uint32_t ah[4][4], alf[4][4];
    {
        int arow = wid * 16 + (lane & 15);
#pragma unroll
        for (int k = 0; k < 4; k++) {
            uint32_t cb = k * 32 + (lane >> 4) * 16;
            uint32_t off = SWZ(arow, cb);
            ldmx4(ah[k], base + 16384 + off);
            ldmx4(alf[k], base + 24576 + off);
        }
    }

    int c0base = wid * 16;
#pragma unroll 2
    for (int nt = 0; nt < 8; nt++) {
        float d[4] = {0.f, 0.f, 0.f, 0.f};
        int prow = nt * 8 + (lane & 7);
#pragma unroll
        for (int k = 0; k < 4; k++) {
            uint32_t cb = k * 32 + ((lane >> 3) & 1) * 16;
            uint32_t off = SWZ(prow, cb);
            uint32_t qf[2], ql[2];
            ldmx2(qf, base + off);
            mma16816(d, ah[k], qf);
            mma16816(d, alf[k], qf);
            ldmx2(ql, base + 8192 + off);
            mma16816(d, ah[k], ql);
        }
        // D[o][p]: rows = channels, cols = pixels (contiguous stores)
        int c0 = c0base + (lane >> 2);
        int col = nt * 8 + 2 * (lane & 3);
        float b0 = bias_s[c0], b1 = bias_s[c0 + 8];
        *(float2*)(out + ((size_t)(n * 64 + c0)) * SS + sIn + col) =
            make_float2(d[0] + b0, d[1] + b0);
        *(float2*)(out + ((size_t)(n * 64 + c0 + 8)) * SS + sIn + col) =
            make_float2(d[2] + b1, d[3] + b1);
    }
}

// ---------------- launch ----------------
extern "C" void kernel_launch(void* const* d_in, const int* in_sizes, int n_in,
                              void* d_out, int out_size) {
    const float* x   = (const float*)d_in[0];
    const float* kow = (const float*)d_in[1];
    const float* kob = (const float*)d_in[2];
    const float* kw  = (const float*)d_in[3];
    const float* qow = (const float*)d_in[4];
    const float* qob = (const float*)d_in[5];
    const float* qw  = (const float*)d_in[6];
    const float* vow = (const float*)d_in[7];
    const float* vob = (const float*)d_in[8];
    const float* vw  = (const float*)d_in[9];
    const float* rpw = (const float*)d_in[10];
    const float* rpb = (const float*)d_in[11];
    float* out = (float*)d_out;

    k_wprep<<<24, 256>>>(kw, qw, vw);
    k_a<<<NS / 64, 128>>>(x, kow, kob, qow, qob, vow, vob);
    k_b<<<1024, 256>>>();
    k_red2<<<544, 256>>>();
    k_fold2<<<32, 256>>>(rpw);
    k_c<<<NS / 64, 128>>>(rpb, out);
}

// round 9
// speedup vs baseline: 2.0519x; 1.2872x over previous
#include <cuda_runtime.h>
#include <cuda_bf16.h>
#include <cuda_fp16.h>
#include <cstdint>

#define NB 4
#define CC 64
#define SS 65536    // H*W
#define NS 262144   // NB*SS

// ---------------- scratch ----------------
__device__ uint32_t g_Yk[(size_t)NS * 32];   // half2-packed, pixel-major [N,S,C/2]
__device__ uint32_t g_Yq[(size_t)NS * 32];
__device__ uint32_t g_Yv[(size_t)NS * 32];
__device__ float g_off[(size_t)6 * NS];      // (ky,kx,qy,qx,vy,vx)
__device__ float g_ctxp[1024 * 1024];        // per-block ctx partials
__device__ float g_zp[1024 * 64];            // per-block Z partials
__device__ float g_ctx[NB * 1024];           // ctx [n][h][k][v]
__device__ float g_Z[NB * 64];
__device__ uint32_t g_Wh[3 * 2048];          // bf16x2 split weights [proj][o][cpair]
__device__ uint32_t g_Wl[3 * 2048];
__device__ uint32_t g_Bh[NB * 2048];         // bf16x2 split folded matrix [n][o][kkpair]
__device__ uint32_t g_Bl[NB * 2048];

// ---------------- mma helpers ----------------
__device__ __forceinline__ uint32_t cvta_s(const void* p) {
    uint32_t a;
    asm("{ .reg .u64 t; cvta.to.shared.u64 t, %1; cvt.u32.u64 %0, t; }" : "=r"(a) : "l"(p));
    return a;
}
__device__ __forceinline__ void ldmx4(uint32_t* r, uint32_t a) {
    asm volatile("ldmatrix.sync.aligned.m8n8.x4.shared.b16 {%0,%1,%2,%3}, [%4];"
                 : "=r"(r[0]), "=r"(r[1]), "=r"(r[2]), "=r"(r[3]) : "r"(a));
}
__device__ __forceinline__ void ldmx2(uint32_t* r, uint32_t a) {
    asm volatile("ldmatrix.sync.aligned.m8n8.x2.shared.b16 {%0,%1}, [%2];"
                 : "=r"(r[0]), "=r"(r[1]) : "r"(a));
}
__device__ __forceinline__ void mma16816(float* d, const uint32_t* a, const uint32_t* b) {
    asm volatile("mma.sync.aligned.m16n8k16.row.col.f32.bf16.bf16.f32 "
                 "{%0,%1,%2,%3},{%4,%5,%6,%7},{%8,%9},{%0,%1,%2,%3};"
                 : "+f"(d[0]), "+f"(d[1]), "+f"(d[2]), "+f"(d[3])
                 : "r"(a[0]), "r"(a[1]), "r"(a[2]), "r"(a[3]), "r"(b[0]), "r"(b[1]));
}
__device__ __forceinline__ uint32_t bfsplit_hi(float v0, float v1, uint32_t& lo) {
    __nv_bfloat16 h0 = __float2bfloat16(v0), h1 = __float2bfloat16(v1);
    __nv_bfloat16 l0 = __float2bfloat16(v0 - __bfloat162float(h0));
    __nv_bfloat16 l1 = __float2bfloat16(v1 - __bfloat162float(h1));
    lo = (uint32_t)__bfloat16_as_ushort(l0) | ((uint32_t)__bfloat16_as_ushort(l1) << 16);
    return (uint32_t)__bfloat16_as_ushort(h0) | ((uint32_t)__bfloat16_as_ushort(h1) << 16);
}
// accumulate 8 fp16 channels (one uint4) with weight w into a[0..7]
__device__ __forceinline__ void acc_h8(float* a, uint4 u, float w) {
    const __half2* h = reinterpret_cast<const __half2*>(&u);
#pragma unroll
    for (int i = 0; i < 4; i++) {
        float2 f = __half22float2(h[i]);
        a[2 * i] += w * f.x; a[2 * i + 1] += w * f.y;
    }
}
// swizzled byte offset within a 64x128B tile
#define SWZ(row, cb) ((uint32_t)((row) * 128 + ((cb) ^ (((row) & 7) << 4))))

// =============== W prep: split weights to bf16 h/l ===============
__global__ __launch_bounds__(256) void k_wprep(const float* __restrict__ kw,
                                               const float* __restrict__ qw,
                                               const float* __restrict__ vw) {
    int idx = blockIdx.x * 256 + threadIdx.x;   // 6144
    int proj = idx >> 11, r = idx & 2047;
    const float* wp = proj == 0 ? kw : (proj == 1 ? qw : vw);
    int o = r >> 5, cp = r & 31;
    float v0 = wp[o * 64 + 2 * cp], v1 = wp[o * 64 + 2 * cp + 1];
    uint32_t lo, hi = bfsplit_hi(v0, v1, lo);
    g_Wh[idx] = hi; g_Wl[idx] = lo;
}

// =============== K_A: offsets + 3 projections via HMMA (split-bf16) ===========
__global__ __launch_bounds__(128) void k_a(
    const float* __restrict__ x,
    const float* __restrict__ kow, const float* __restrict__ kob,
    const float* __restrict__ qow, const float* __restrict__ qob,
    const float* __restrict__ vow, const float* __restrict__ vob) {
    __shared__ __align__(16) unsigned char sm[32768 + 1600];
    float* owf = (float*)(sm + 32768);          // [6][64]
    float* obf = (float*)(sm + 32768 + 1536);   // [6]

    int tid = threadIdx.x;
    int lane = tid & 31, wid = tid >> 5;
    uint32_t base = cvta_s(sm);

    int pg0 = blockIdx.x * 64;
    int n   = pg0 >> 16;
    int sIn = pg0 & 65535;

    const float* xb = x + (size_t)n * CC * SS + sIn;
#pragma unroll
    for (int it = 0; it < 16; it++) {
        int idx = tid + 128 * it;               // 2048 c-pairs
        int cp = idx >> 6, p = idx & 63;
        float v0 = xb[(size_t)(2 * cp) * SS + p];
        float v1 = xb[(size_t)(2 * cp + 1) * SS + p];
        uint32_t lo, hi = bfsplit_hi(v0, v1, lo);
        uint32_t off = SWZ(p, cp * 4);
        *(uint32_t*)(sm + off) = hi;
        *(uint32_t*)(sm + 8192 + off) = lo;
    }
    if (tid < 128) { owf[tid] = kow[tid]; owf[128 + tid] = qow[tid]; owf[256 + tid] = vow[tid]; }
    if (tid < 2) { obf[tid] = kob[tid]; obf[2 + tid] = qob[tid]; obf[4 + tid] = vob[tid]; }
    __syncthreads();

    // ---- offsets (reconstruct x = xh + xl)
    {
        int p = tid >> 1, half = tid & 1;
        float od[6] = {0.f, 0.f, 0.f, 0.f, 0.f, 0.f};
#pragma unroll
        for (int i = 0; i < 16; i++) {
            uint32_t off = SWZ(p, half * 64 + 4 * i);
            uint32_t hh = *(const uint32_t*)(sm + off);
            uint32_t ll = *(const uint32_t*)(sm + 8192 + off);
            __nv_bfloat162 h2 = *reinterpret_cast<__nv_bfloat162*>(&hh);
            __nv_bfloat162 l2 = *reinterpret_cast<__nv_bfloat162*>(&ll);
            float x0 = __low2float(h2) + __low2float(l2);
            float x1 = __high2float(h2) + __high2float(l2);
            int c = half * 32 + 2 * i;
#pragma unroll
            for (int d = 0; d < 6; d++)
                od[d] += x0 * owf[d * 64 + c] + x1 * owf[d * 64 + c + 1];
        }
#pragma unroll
        for (int d = 0; d < 6; d++) od[d] += __shfl_xor_sync(0xffffffffu, od[d], 1);
        if (half == 0) {
#pragma unroll
            for (int d = 0; d < 6; d++)
                g_off[(size_t)d * NS + pg0 + p] = od[d] + obf[d];
        }
    }

    // ---- A fragments held across all projections
    uint32_t ah[4][4], alf[4][4];
    {
        int arow = wid * 16 + (lane & 15);
#pragma unroll
        for (int k = 0; k < 4; k++) {
            uint32_t cb = k * 32 + (lane >> 4) * 16;
            uint32_t off = SWZ(arow, cb);
            ldmx4(ah[k], base + off);
            ldmx4(alf[k], base + 8192 + off);
        }
    }

    uint32_t* yd3[3] = {g_Yk, g_Yq, g_Yv};
    for (int pr = 0; pr < 3; pr++) {
        __syncthreads();
        const uint32_t* wh = g_Wh + pr * 2048;
        const uint32_t* wl = g_Wl + pr * 2048;
#pragma unroll
        for (int it = 0; it < 16; it++) {
            int idx = tid + 128 * it;
            int o = idx >> 5, cp = idx & 31;
            uint32_t off = SWZ(o, cp * 4);
            *(uint32_t*)(sm + 16384 + off) = wh[idx];
            *(uint32_t*)(sm + 24576 + off) = wl[idx];
        }
        __syncthreads();

        uint32_t* yb = yd3[pr] + (size_t)pg0 * 32;
        int p0 = wid * 16;
#pragma unroll 2
        for (int nt = 0; nt < 8; nt++) {
            float d[4] = {0.f, 0.f, 0.f, 0.f};
            int orow = nt * 8 + (lane & 7);
#pragma unroll
            for (int k = 0; k < 4; k++) {
                uint32_t cb = k * 32 + ((lane >> 3) & 1) * 16;
                uint32_t off = SWZ(orow, cb);
                uint32_t bh[2], bl[2];
                ldmx2(bh, base + 16384 + off);
                mma16816(d, ah[k], bh);
                mma16816(d, alf[k], bh);
                ldmx2(bl, base + 24576 + off);
                mma16816(d, ah[k], bl);
            }
            int r0 = p0 + (lane >> 2);
            int colp = (nt * 8 + 2 * (lane & 3)) >> 1;   // half2 index
            __half2 h01 = __floats2half2_rn(d[0], d[1]);
            __half2 h23 = __floats2half2_rn(d[2], d[3]);
            yb[(size_t)r0 * 32 + colp] = *reinterpret_cast<uint32_t*>(&h01);
            yb[(size_t)(r0 + 8) * 32 + colp] = *reinterpret_cast<uint32_t*>(&h23);
        }
    }
}

// =============== K_B: gather K,V (fp16) + exp + context/Z partials ===========
__global__ __launch_bounds__(256) void k_b() {
    __shared__ float Ke[64][68];
    __shared__ float Vs[64][68];

    int tid = threadIdx.x;
    int h = tid >> 6, k = (tid >> 2) & 15, vg = tid & 3;
    int p4 = tid >> 2, qd = tid & 3;

    float a0 = 0.f, a1 = 0.f, a2 = 0.f, a3 = 0.f, z = 0.f;

    for (int tile = 0; tile < 4; tile++) {
        int pg0 = (blockIdx.x * 4 + tile) * 64;
        int n   = pg0 >> 16;
        int sIn = pg0 & 65535;
        long pG = (long)pg0 + p4;
        int s   = sIn + p4;
        int yI  = s >> 8, xI = s & 255;

#pragma unroll
        for (int tv = 0; tv < 2; tv++) {
            const uint32_t* Ysrc = tv ? g_Yv : g_Yk;
            int dB = tv ? 4 : 0;
            float oy = g_off[(size_t)dB * NS + pG];
            float ox = g_off[(size_t)(dB + 1) * NS + pG];
            float py = (float)yI + oy, px = (float)xI + ox;
            float y0f = floorf(py), x0f = floorf(px);
            int iy0 = (int)y0f, ix0 = (int)x0f;
            float ty = py - y0f, tx = px - x0f;
            float wg[4] = {(1.f - ty) * (1.f - tx), (1.f - ty) * tx,
                           ty * (1.f - tx), ty * tx};
            float acc[16];
#pragma unroll
            for (int i = 0; i < 16; i++) acc[i] = 0.f;
#pragma unroll
            for (int t = 0; t < 4; t++) {
                int iy = iy0 + (t >> 1), ix = ix0 + (t & 1);
                if (iy >= 0 && iy < 256 && ix >= 0 && ix < 256) {
                    const uint4* tp = (const uint4*)(Ysrc +
                        ((((size_t)n << 16) | ((size_t)iy << 8) | (size_t)ix) * 32) + qd * 8);
                    float w = wg[t];
                    acc_h8(acc, tp[0], w);
                    acc_h8(acc + 8, tp[1], w);
                }
            }
            if (tv == 0) {
#pragma unroll
                for (int i = 0; i < 16; i++) Ke[p4][qd * 16 + i] = __expf(acc[i]);
            } else {
#pragma unroll
                for (int i = 0; i < 4; i++)
                    *(float4*)&Vs[p4][qd * 16 + 4 * i] = *(float4*)&acc[4 * i];
            }
        }
        __syncthreads();

#pragma unroll 8
        for (int p = 0; p < 64; p++) {
            float kv = Ke[p][h * 16 + k];
            float4 v4 = *(const float4*)&Vs[p][h * 16 + vg * 4];
            a0 += kv * v4.x; a1 += kv * v4.y; a2 += kv * v4.z; a3 += kv * v4.w;
            z += kv;
        }
        __syncthreads();
    }

    size_t base = (size_t)blockIdx.x * 1024 + h * 256 + k * 16 + vg * 4;
    g_ctxp[base + 0] = a0; g_ctxp[base + 1] = a1;
    g_ctxp[base + 2] = a2; g_ctxp[base + 3] = a3;
    if (vg == 0) g_zp[blockIdx.x * 64 + h * 16 + k] = z;
}

// =============== reduce partials: warp per row ===============
__global__ __launch_bounds__(256) void k_red2() {
    int wid = threadIdx.x >> 5, lid = threadIdx.x & 31;
    if (blockIdx.x < 512) {
        int row = blockIdx.x * 8 + wid;            // 4096 ctx rows
        int n = row >> 10, idx = row & 1023;
        float v = 0.f;
#pragma unroll
        for (int j = 0; j < 8; j++)
            v += g_ctxp[((size_t)(n * 256 + j * 32 + lid)) * 1024 + idx];
#pragma unroll
        for (int o = 16; o > 0; o >>= 1) v += __shfl_xor_sync(0xffffffffu, v, o);
        if (lid == 0) g_ctx[row] = v;
    } else {
        int zrow = (blockIdx.x - 512) * 8 + wid;   // 256 z rows
        int n = zrow >> 6, kk = zrow & 63;
        float v = 0.f;
#pragma unroll
        for (int j = 0; j < 8; j++)
            v += g_zp[(n * 256 + j * 32 + lid) * 64 + kk];
#pragma unroll
        for (int o = 16; o > 0; o >>= 1) v += __shfl_xor_sync(0xffffffffu, v, o);
        if (lid == 0) g_Z[zrow] = v;
    }
}

// =============== fold: B[n][o][kk] -> split bf16 h/l pairs ===============
__global__ __launch_bounds__(256) void k_fold2(const float* __restrict__ rpw) {
    int idx = blockIdx.x * 256 + threadIdx.x;    // 8192 pairs
    int n = idx >> 11, r = idx & 2047;
    int o = r >> 5, cp = r & 31;
    float b2[2];
#pragma unroll
    for (int e = 0; e < 2; e++) {
        int kk = 2 * cp + e;
        int h = kk >> 4, k = kk & 15;
        const float* cx = g_ctx + n * 1024 + h * 256 + k * 16;
        const float* wr = rpw + o * 64 + h * 16;
        float a = 0.f;
#pragma unroll
        for (int v = 0; v < 16; v++) a += wr[v] * cx[v];
        b2[e] = a / g_Z[n * 64 + kk];
    }
    uint32_t lo, hi = bfsplit_hi(b2[0], b2[1], lo);
    g_Bh[idx] = hi; g_Bl[idx] = lo;
}

// =============== K_C: gather Q (fp16) + reg softmax + HMMA B-GEMM ===========
__global__ __launch_bounds__(128) void k_c(const float* __restrict__ rpb,
                                           float* __restrict__ out) {
    __shared__ __align__(16) unsigned char sm[32768 + 256];
    float* bias_s = (float*)(sm + 32768);

    int tid = threadIdx.x;
    int lane = tid & 31, wid = tid >> 5;
    uint32_t base = cvta_s(sm);

    int pg0 = blockIdx.x * 64;
    int n   = pg0 >> 16;
    int sIn = pg0 & 65535;

    const uint32_t* bh = g_Bh + n * 2048;
    const uint32_t* bl = g_Bl + n * 2048;
#pragma unroll
    for (int it = 0; it < 16; it++) {
        int idx = tid + 128 * it;
        int o = idx >> 5, cp = idx & 31;
        uint32_t off = SWZ(o, cp * 4);
        *(uint32_t*)(sm + 16384 + off) = bh[idx];
        *(uint32_t*)(sm + 24576 + off) = bl[idx];
    }
    if (tid < 64) bias_s[tid] = rpb[tid];

    // ---- gather q (fp16) + in-register softmax + split store
    {
        int p2 = tid >> 1, qh = tid & 1;
        long pG = (long)pg0 + p2;
        int s = sIn + p2;
        int yI = s >> 8, xI = s & 255;
        float oy = g_off[(size_t)2 * NS + pG];
        float ox = g_off[(size_t)3 * NS + pG];
        float py = (float)yI + oy, px = (float)xI + ox;
        float y0f = floorf(py), x0f = floorf(px);
        int iy0 = (int)y0f, ix0 = (int)x0f;
        float ty = py - y0f, tx = px - x0f;
        float wg[4] = {(1.f - ty) * (1.f - tx), (1.f - ty) * tx,
                       ty * (1.f - tx), ty * tx};
        float acc[32];
#pragma unroll
        for (int i = 0; i < 32; i++) acc[i] = 0.f;
#pragma unroll
        for (int t = 0; t < 4; t++) {
            int iy = iy0 + (t >> 1), ix = ix0 + (t & 1);
            if (iy >= 0 && iy < 256 && ix >= 0 && ix < 256) {
                const uint4* tp = (const uint4*)(g_Yq +
                    ((((size_t)n << 16) | ((size_t)iy << 8) | (size_t)ix) * 32) + qh * 16);
                float w = wg[t];
#pragma unroll
                for (int i = 0; i < 4; i++) acc_h8(acc + 8 * i, tp[i], w);
            }
        }
#pragma unroll
        for (int hh = 0; hh < 2; hh++) {
            float* v = acc + hh * 16;
            float m = v[0];
#pragma unroll
            for (int i = 1; i < 16; i++) m = fmaxf(m, v[i]);
            float sum = 0.f;
#pragma unroll
            for (int i = 0; i < 16; i++) { v[i] = __expf(v[i] - m); sum += v[i]; }
            float inv = 1.f / sum;
#pragma unroll
            for (int i = 0; i < 16; i++) v[i] *= inv;
        }
#pragma unroll
        for (int i = 0; i < 16; i++) {
            uint32_t lo, hi = bfsplit_hi(acc[2 * i], acc[2 * i + 1], lo);
            uint32_t off = SWZ(p2, (qh * 16 + i) * 4);
            *(uint32_t*)(sm + off) = hi;
            *(uint32_t*)(sm + 8192 + off) = lo;
        }
    }
    __syncthreads();

    // ---- A frags = B-matrix rows (channels)
    uint32_t ah[4][4], alf[4][4];
    {
        int arow = wid * 16 + (lane & 15);
#pragma unroll
        for (int k = 0; k < 4; k++) {
            uint32_t cb = k * 32 + (lane >> 4) * 16;
            uint32_t off = SWZ(arow, cb);
            ldmx4(ah[k], base + 16384 + off);
            ldmx4(alf[k], base + 24576 + off);
        }
    }

    int c0base = wid * 16;
#pragma unroll 2
    for (int nt = 0; nt < 8; nt++) {
        float d[4] = {0.f, 0.f, 0.f, 0.f};
        int prow = nt * 8 + (lane & 7);
#pragma unroll
        for (int k = 0; k < 4; k++) {
            uint32_t cb = k * 32 + ((lane >> 3) & 1) * 16;
            uint32_t off = SWZ(prow, cb);
            uint32_t qf[2], ql[2];
            ldmx2(qf, base + off);
            mma16816(d, ah[k], qf);
            mma16816(d, alf[k], qf);
            ldmx2(ql, base + 8192 + off);
            mma16816(d, ah[k], ql);
        }
        int c0 = c0base + (lane >> 2);
        int col = nt * 8 + 2 * (lane & 3);
        float b0 = bias_s[c0], b1 = bias_s[c0 + 8];
        *(float2*)(out + ((size_t)(n * 64 + c0)) * SS + sIn + col) =
            make_float2(d[0] + b0, d[1] + b0);
        *(float2*)(out + ((size_t)(n * 64 + c0 + 8)) * SS + sIn + col) =
            make_float2(d[2] + b1, d[3] + b1);
    }
}

// ---------------- launch ----------------
extern "C" void kernel_launch(void* const* d_in, const int* in_sizes, int n_in,
                              void* d_out, int out_size) {
    const float* x   = (const float*)d_in[0];
    const float* kow = (const float*)d_in[1];
    const float* kob = (const float*)d_in[2];
    const float* kw  = (const float*)d_in[3];
    const float* qow = (const float*)d_in[4];
    const float* qob = (const float*)d_in[5];
    const float* qw  = (const float*)d_in[6];
    const float* vow = (const float*)d_in[7];
    const float* vob = (const float*)d_in[8];
    const float* vw  = (const float*)d_in[9];
    const float* rpw = (const float*)d_in[10];
    const float* rpb = (const float*)d_in[11];
    float* out = (float*)d_out;

    k_wprep<<<24, 256>>>(kw, qw, vw);
    k_a<<<NS / 64, 128>>>(x, kow, kob, qow, qob, vow, vob);
    k_b<<<1024, 256>>>();
    k_red2<<<544, 256>>>();
    k_fold2<<<32, 256>>>(rpw);
    k_c<<<NS / 64, 128>>>(rpb, out);
}

// round 10
// speedup vs baseline: 2.0712x; 1.0094x over previous
#include <cuda_runtime.h>
#include <cuda_bf16.h>
#include <cuda_fp16.h>
#include <cstdint>

#define NB 4
#define CC 64
#define SS 65536    // H*W
#define NS 262144   // NB*SS

// ---------------- scratch ----------------
__device__ uint32_t g_Yk[(size_t)NS * 32];   // half2-packed, pixel-major [N,S,C/2]
__device__ uint32_t g_Yq[(size_t)NS * 32];
__device__ uint32_t g_Yv[(size_t)NS * 32];
__device__ float g_off[(size_t)6 * NS];      // (ky,kx,qy,qx,vy,vx)
__device__ float g_ctxp[1024 * 1024];        // per-block ctx partials
__device__ float g_zp[1024 * 64];            // per-block Z partials
__device__ float g_ctx[NB * 1024];           // ctx [n][h][k][v]
__device__ float g_Z[NB * 64];
__device__ uint32_t g_Wh[3 * 2048];          // bf16x2 split weights [proj][o][cpair]
__device__ uint32_t g_Wl[3 * 2048];
__device__ uint32_t g_Bh[NB * 2048];         // bf16x2 split folded matrix [n][o][kkpair]
__device__ uint32_t g_Bl[NB * 2048];

// ---------------- mma helpers ----------------
__device__ __forceinline__ uint32_t cvta_s(const void* p) {
    uint32_t a;
    asm("{ .reg .u64 t; cvta.to.shared.u64 t, %1; cvt.u32.u64 %0, t; }" : "=r"(a) : "l"(p));
    return a;
}
__device__ __forceinline__ void ldmx4(uint32_t* r, uint32_t a) {
    asm volatile("ldmatrix.sync.aligned.m8n8.x4.shared.b16 {%0,%1,%2,%3}, [%4];"
                 : "=r"(r[0]), "=r"(r[1]), "=r"(r[2]), "=r"(r[3]) : "r"(a));
}
__device__ __forceinline__ void ldmx2(uint32_t* r, uint32_t a) {
    asm volatile("ldmatrix.sync.aligned.m8n8.x2.shared.b16 {%0,%1}, [%2];"
                 : "=r"(r[0]), "=r"(r[1]) : "r"(a));
}
__device__ __forceinline__ void mma16816(float* d, const uint32_t* a, const uint32_t* b) {
    asm volatile("mma.sync.aligned.m16n8k16.row.col.f32.bf16.bf16.f32 "
                 "{%0,%1,%2,%3},{%4,%5,%6,%7},{%8,%9},{%0,%1,%2,%3};"
                 : "+f"(d[0]), "+f"(d[1]), "+f"(d[2]), "+f"(d[3])
                 : "r"(a[0]), "r"(a[1]), "r"(a[2]), "r"(a[3]), "r"(b[0]), "r"(b[1]));
}
__device__ __forceinline__ uint32_t bfsplit_hi(float v0, float v1, uint32_t& lo) {
    __nv_bfloat16 h0 = __float2bfloat16(v0), h1 = __float2bfloat16(v1);
    __nv_bfloat16 l0 = __float2bfloat16(v0 - __bfloat162float(h0));
    __nv_bfloat16 l1 = __float2bfloat16(v1 - __bfloat162float(h1));
    lo = (uint32_t)__bfloat16_as_ushort(l0) | ((uint32_t)__bfloat16_as_ushort(l1) << 16);
    return (uint32_t)__bfloat16_as_ushort(h0) | ((uint32_t)__bfloat16_as_ushort(h1) << 16);
}
__device__ __forceinline__ uint32_t pack_bf16(float lo, float hi) {
    __nv_bfloat162 b = __floats2bfloat162_rn(lo, hi);
    return *reinterpret_cast<uint32_t*>(&b);
}
// accumulate 8 fp16 channels (one uint4) with weight w into a[0..7]
__device__ __forceinline__ void acc_h8(float* a, uint4 u, float w) {
    const __half2* h = reinterpret_cast<const __half2*>(&u);
#pragma unroll
    for (int i = 0; i < 4; i++) {
        float2 f = __half22float2(h[i]);
        a[2 * i] += w * f.x; a[2 * i + 1] += w * f.y;
    }
}
// swizzled byte offset within a 64x128B tile
#define SWZ(row, cb) ((uint32_t)((row) * 128 + ((cb) ^ (((row) & 7) << 4))))

// =============== W prep: split weights to bf16 h/l ===============
__global__ __launch_bounds__(256) void k_wprep(const float* __restrict__ kw,
                                               const float* __restrict__ qw,
                                               const float* __restrict__ vw) {
    int idx = blockIdx.x * 256 + threadIdx.x;   // 6144
    int proj = idx >> 11, r = idx & 2047;
    const float* wp = proj == 0 ? kw : (proj == 1 ? qw : vw);
    int o = r >> 5, cp = r & 31;
    float v0 = wp[o * 64 + 2 * cp], v1 = wp[o * 64 + 2 * cp + 1];
    uint32_t lo, hi = bfsplit_hi(v0, v1, lo);
    g_Wh[idx] = hi; g_Wl[idx] = lo;
}

// =============== K_A: offsets + 3 projections via HMMA (split-bf16) ===========
__global__ __launch_bounds__(128) void k_a(
    const float* __restrict__ x,
    const float* __restrict__ kow, const float* __restrict__ kob,
    const float* __restrict__ qow, const float* __restrict__ qob,
    const float* __restrict__ vow, const float* __restrict__ vob) {
    __shared__ __align__(16) unsigned char sm[32768 + 1600];
    float* owf = (float*)(sm + 32768);          // [6][64]
    float* obf = (float*)(sm + 32768 + 1536);   // [6]

    int tid = threadIdx.x;
    int lane = tid & 31, wid = tid >> 5;
    uint32_t base = cvta_s(sm);

    int pg0 = blockIdx.x * 64;
    int n   = pg0 >> 16;
    int sIn = pg0 & 65535;

    const float* xb = x + (size_t)n * CC * SS + sIn;
#pragma unroll
    for (int it = 0; it < 16; it++) {
        int idx = tid + 128 * it;               // 2048 c-pairs
        int cp = idx >> 6, p = idx & 63;
        float v0 = xb[(size_t)(2 * cp) * SS + p];
        float v1 = xb[(size_t)(2 * cp + 1) * SS + p];
        uint32_t lo, hi = bfsplit_hi(v0, v1, lo);
        uint32_t off = SWZ(p, cp * 4);
        *(uint32_t*)(sm + off) = hi;
        *(uint32_t*)(sm + 8192 + off) = lo;
    }
    if (tid < 128) { owf[tid] = kow[tid]; owf[128 + tid] = qow[tid]; owf[256 + tid] = vow[tid]; }
    if (tid < 2) { obf[tid] = kob[tid]; obf[2 + tid] = qob[tid]; obf[4 + tid] = vob[tid]; }
    __syncthreads();

    // ---- offsets (reconstruct x = xh + xl)
    {
        int p = tid >> 1, half = tid & 1;
        float od[6] = {0.f, 0.f, 0.f, 0.f, 0.f, 0.f};
#pragma unroll
        for (int i = 0; i < 16; i++) {
            uint32_t off = SWZ(p, half * 64 + 4 * i);
            uint32_t hh = *(const uint32_t*)(sm + off);
            uint32_t ll = *(const uint32_t*)(sm + 8192 + off);
            __nv_bfloat162 h2 = *reinterpret_cast<__nv_bfloat162*>(&hh);
            __nv_bfloat162 l2 = *reinterpret_cast<__nv_bfloat162*>(&ll);
            float x0 = __low2float(h2) + __low2float(l2);
            float x1 = __high2float(h2) + __high2float(l2);
            int c = half * 32 + 2 * i;
#pragma unroll
            for (int d = 0; d < 6; d++)
                od[d] += x0 * owf[d * 64 + c] + x1 * owf[d * 64 + c + 1];
        }
#pragma unroll
        for (int d = 0; d < 6; d++) od[d] += __shfl_xor_sync(0xffffffffu, od[d], 1);
        if (half == 0) {
#pragma unroll
            for (int d = 0; d < 6; d++)
                g_off[(size_t)d * NS + pg0 + p] = od[d] + obf[d];
        }
    }

    // ---- A fragments held across all projections
    uint32_t ah[4][4], alf[4][4];
    {
        int arow = wid * 16 + (lane & 15);
#pragma unroll
        for (int k = 0; k < 4; k++) {
            uint32_t cb = k * 32 + (lane >> 4) * 16;
            uint32_t off = SWZ(arow, cb);
            ldmx4(ah[k], base + off);
            ldmx4(alf[k], base + 8192 + off);
        }
    }

    uint32_t* yd3[3] = {g_Yk, g_Yq, g_Yv};
    for (int pr = 0; pr < 3; pr++) {
        __syncthreads();
        const uint32_t* wh = g_Wh + pr * 2048;
        const uint32_t* wl = g_Wl + pr * 2048;
#pragma unroll
        for (int it = 0; it < 16; it++) {
            int idx = tid + 128 * it;
            int o = idx >> 5, cp = idx & 31;
            uint32_t off = SWZ(o, cp * 4);
            *(uint32_t*)(sm + 16384 + off) = wh[idx];
            *(uint32_t*)(sm + 24576 + off) = wl[idx];
        }
        __syncthreads();

        uint32_t* yb = yd3[pr] + (size_t)pg0 * 32;
        int p0 = wid * 16;
#pragma unroll 2
        for (int nt = 0; nt < 8; nt++) {
            float d[4] = {0.f, 0.f, 0.f, 0.f};
            int orow = nt * 8 + (lane & 7);
#pragma unroll
            for (int k = 0; k < 4; k++) {
                uint32_t cb = k * 32 + ((lane >> 3) & 1) * 16;
                uint32_t off = SWZ(orow, cb);
                uint32_t bh[2], bl[2];
                ldmx2(bh, base + 16384 + off);
                mma16816(d, ah[k], bh);
                mma16816(d, alf[k], bh);
                ldmx2(bl, base + 24576 + off);
                mma16816(d, ah[k], bl);
            }
            int r0 = p0 + (lane >> 2);
            int colp = (nt * 8 + 2 * (lane & 3)) >> 1;   // half2 index
            __half2 h01 = __floats2half2_rn(d[0], d[1]);
            __half2 h23 = __floats2half2_rn(d[2], d[3]);
            yb[(size_t)r0 * 32 + colp] = *reinterpret_cast<uint32_t*>(&h01);
            yb[(size_t)(r0 + 8) * 32 + colp] = *reinterpret_cast<uint32_t*>(&h23);
        }
    }
}

// =============== K_B: gather K,V (fp16) + exp + HMMA context ===============
// 256 threads; 4 tiles of 64 px; ctx fragments live in registers across tiles.
// smem: Ke bf16 tile [64ch x 64px] @0 (8KB), Vs @8192 (8KB); reused for z-reduce.
__global__ __launch_bounds__(256) void k_b() {
    __shared__ __align__(16) unsigned char sm[16384 + 1152];

    int tid = threadIdx.x;
    int lane = tid & 31, wrp = tid >> 5;
    uint32_t base = cvta_s(sm);

    int p4 = tid >> 2, qd = tid & 3;      // gather role: pixel, channel-quarter
    int head = wrp & 3, nh = wrp >> 2;    // mma role: head, v-half
    bool evenp = (p4 & 1) == 0;

    float zp[16];
#pragma unroll
    for (int i = 0; i < 16; i++) zp[i] = 0.f;
    float d[4] = {0.f, 0.f, 0.f, 0.f};    // ctx fragment, accumulated across tiles

    for (int tile = 0; tile < 4; tile++) {
        int pg0 = (blockIdx.x * 4 + tile) * 64;
        int n   = pg0 >> 16;
        int sIn = pg0 & 65535;
        long pG = (long)pg0 + p4;
        int s   = sIn + p4;
        int yI  = s >> 8, xI = s & 255;

#pragma unroll
        for (int tv = 0; tv < 2; tv++) {
            const uint32_t* Ysrc = tv ? g_Yv : g_Yk;
            int dB = tv ? 4 : 0;
            float oy = g_off[(size_t)dB * NS + pG];
            float ox = g_off[(size_t)(dB + 1) * NS + pG];
            float py = (float)yI + oy, px = (float)xI + ox;
            float y0f = floorf(py), x0f = floorf(px);
            int iy0 = (int)y0f, ix0 = (int)x0f;
            float ty = py - y0f, tx = px - x0f;
            float wg[4] = {(1.f - ty) * (1.f - tx), (1.f - ty) * tx,
                           ty * (1.f - tx), ty * tx};
            float acc[16];
#pragma unroll
            for (int i = 0; i < 16; i++) acc[i] = 0.f;
#pragma unroll
            for (int t = 0; t < 4; t++) {
                int iy = iy0 + (t >> 1), ix = ix0 + (t & 1);
                if (iy >= 0 && iy < 256 && ix >= 0 && ix < 256) {
                    const uint4* tp = (const uint4*)(Ysrc +
                        ((((size_t)n << 16) | ((size_t)iy << 8) | (size_t)ix) * 32) + qd * 8);
                    float w = wg[t];
                    acc_h8(acc, tp[0], w);
                    acc_h8(acc + 8, tp[1], w);
                }
            }
            if (tv == 0) {
#pragma unroll
                for (int i = 0; i < 16; i++) {
                    acc[i] = __expf(acc[i]);
                    zp[i] += acc[i];
                }
            }
            // pack adjacent-pixel pairs to bf16, store channel-major swizzled tile
            uint32_t tbase = tv ? 8192u : 0u;
#pragma unroll
            for (int i = 0; i < 16; i++) {
                float other = __shfl_xor_sync(0xffffffffu, acc[i], 4);
                if ((i < 8) == evenp) {
                    float lo = evenp ? acc[i] : other;
                    float hi = evenp ? other : acc[i];
                    uint32_t off = SWZ(qd * 16 + i, (p4 >> 1) * 4);
                    *(uint32_t*)(sm + tbase + off) = pack_bf16(lo, hi);
                }
            }
        }
        __syncthreads();

        // ---- HMMA: ctx[head] += Ke[head] · Vs[head]^T over this tile's 64 px
        {
            int arow = head * 16 + (lane & 15);
            int brow = head * 16 + nh * 8 + (lane & 7);
#pragma unroll
            for (int kc = 0; kc < 4; kc++) {
                uint32_t acb = kc * 32 + (lane >> 4) * 16;
                uint32_t bcb = kc * 32 + ((lane >> 3) & 1) * 16;
                uint32_t afr[4], bfr[2];
                ldmx4(afr, base + SWZ(arow, acb));
                ldmx2(bfr, base + 8192 + SWZ(brow, bcb));
                mma16816(d, afr, bfr);
            }
        }
        __syncthreads();
    }

    // ---- write ctx partials
    {
        size_t cb = (size_t)blockIdx.x * 1024 + head * 256;
        int krow = lane >> 2, vcol = nh * 8 + 2 * (lane & 3);
        g_ctxp[cb + krow * 16 + vcol]           = d[0];
        g_ctxp[cb + krow * 16 + vcol + 1]       = d[1];
        g_ctxp[cb + (krow + 8) * 16 + vcol]     = d[2];
        g_ctxp[cb + (krow + 8) * 16 + vcol + 1] = d[3];
    }

    // ---- z reduction (reuse tile smem as float buffers)
    __syncthreads();
    float* zbuf = (float*)sm;                   // [64 px][64 ch]
#pragma unroll
    for (int i = 0; i < 16; i++) zbuf[p4 * 64 + qd * 16 + i] = zp[i];
    __syncthreads();
    {
        int ch = tid & 63, q = tid >> 6;
        float ssum = 0.f;
#pragma unroll
        for (int r = 0; r < 16; r++) ssum += zbuf[(q * 16 + r) * 64 + ch];
        float* zr2 = (float*)(sm + 16384);      // [4][64]
        zr2[q * 64 + ch] = ssum;
        __syncthreads();
        if (tid < 64)
            g_zp[blockIdx.x * 64 + tid] =
                zr2[tid] + zr2[64 + tid] + zr2[128 + tid] + zr2[192 + tid];
    }
}

// =============== reduce partials: warp per row ===============
__global__ __launch_bounds__(256) void k_red2() {
    int wid = threadIdx.x >> 5, lid = threadIdx.x & 31;
    if (blockIdx.x < 512) {
        int row = blockIdx.x * 8 + wid;            // 4096 ctx rows
        int n = row >> 10, idx = row & 1023;
        float v = 0.f;
#pragma unroll
        for (int j = 0; j < 8; j++)
            v += g_ctxp[((size_t)(n * 256 + j * 32 + lid)) * 1024 + idx];
#pragma unroll
        for (int o = 16; o > 0; o >>= 1) v += __shfl_xor_sync(0xffffffffu, v, o);
        if (lid == 0) g_ctx[row] = v;
    } else {
        int zrow = (blockIdx.x - 512) * 8 + wid;   // 256 z rows
        int n = zrow >> 6, kk = zrow & 63;
        float v = 0.f;
#pragma unroll
        for (int j = 0; j < 8; j++)
            v += g_zp[(n * 256 + j * 32 + lid) * 64 + kk];
#pragma unroll
        for (int o = 16; o > 0; o >>= 1) v += __shfl_xor_sync(0xffffffffu, v, o);
        if (lid == 0) g_Z[zrow] = v;
    }
}

// =============== fold: B[n][o][kk] -> split bf16 h/l pairs ===============
__global__ __launch_bounds__(256) void k_fold2(const float* __restrict__ rpw) {
    int idx = blockIdx.x * 256 + threadIdx.x;    // 8192 pairs
    int n = idx >> 11, r = idx & 2047;
    int o = r >> 5, cp = r & 31;
    float b2[2];
#pragma unroll
    for (int e = 0; e < 2; e++) {
        int kk = 2 * cp + e;
        int h = kk >> 4, k = kk & 15;
        const float* cx = g_ctx + n * 1024 + h * 256 + k * 16;
        const float* wr = rpw + o * 64 + h * 16;
        float a = 0.f;
#pragma unroll
        for (int v = 0; v < 16; v++) a += wr[v] * cx[v];
        b2[e] = a / g_Z[n * 64 + kk];
    }
    uint32_t lo, hi = bfsplit_hi(b2[0], b2[1], lo);
    g_Bh[idx] = hi; g_Bl[idx] = lo;
}

// =============== K_C: gather Q (fp16) + reg softmax + HMMA B-GEMM ===========
__global__ __launch_bounds__(128) void k_c(const float* __restrict__ rpb,
                                           float* __restrict__ out) {
    __shared__ __align__(16) unsigned char sm[32768 + 256];
    float* bias_s = (float*)(sm + 32768);

    int tid = threadIdx.x;
    int lane = tid & 31, wid = tid >> 5;
    uint32_t base = cvta_s(sm);

    int pg0 = blockIdx.x * 64;
    int n   = pg0 >> 16;
    int sIn = pg0 & 65535;

    const uint32_t* bh = g_Bh + n * 2048;
    const uint32_t* bl = g_Bl + n * 2048;
#pragma unroll
    for (int it = 0; it < 16; it++) {
        int idx = tid + 128 * it;
        int o = idx >> 5, cp = idx & 31;
        uint32_t off = SWZ(o, cp * 4);
        *(uint32_t*)(sm + 16384 + off) = bh[idx];
        *(uint32_t*)(sm + 24576 + off) = bl[idx];
    }
    if (tid < 64) bias_s[tid] = rpb[tid];

    // ---- gather q (fp16) + in-register softmax + split store
    {
        int p2 = tid >> 1, qh = tid & 1;
        long pG = (long)pg0 + p2;
        int s = sIn + p2;
        int yI = s >> 8, xI = s & 255;
        float oy = g_off[(size_t)2 * NS + pG];
        float ox = g_off[(size_t)3 * NS + pG];
        float py = (float)yI + oy, px = (float)xI + ox;
        float y0f = floorf(py), x0f = floorf(px);
        int iy0 = (int)y0f, ix0 = (int)x0f;
        float ty = py - y0f, tx = px - x0f;
        float wg[4] = {(1.f - ty) * (1.f - tx), (1.f - ty) * tx,
                       ty * (1.f - tx), ty * tx};
        float acc[32];
#pragma unroll
        for (int i = 0; i < 32; i++) acc[i] = 0.f;
#pragma unroll
        for (int t = 0; t < 4; t++) {
            int iy = iy0 + (t >> 1), ix = ix0 + (t & 1);
            if (iy >= 0 && iy < 256 && ix >= 0 && ix < 256) {
                const uint4* tp = (const uint4*)(g_Yq +
                    ((((size_t)n << 16) | ((size_t)iy << 8) | (size_t)ix) * 32) + qh * 16);
                float w = wg[t];
#pragma unroll
                for (int i = 0; i < 4; i++) acc_h8(acc + 8 * i, tp[i], w);
            }
        }
#pragma unroll
        for (int hh = 0; hh < 2; hh++) {
            float* v = acc + hh * 16;
            float m = v[0];
#pragma unroll
            for (int i = 1; i < 16; i++) m = fmaxf(m, v[i]);
            float sum = 0.f;
#pragma unroll
            for (int i = 0; i < 16; i++) { v[i] = __expf(v[i] - m); sum += v[i]; }
            float inv = 1.f / sum;
#pragma unroll
            for (int i = 0; i < 16; i++) v[i] *= inv;
        }
#pragma unroll
        for (int i = 0; i < 16; i++) {
            uint32_t lo, hi = bfsplit_hi(acc[2 * i], acc[2 * i + 1], lo);
            uint32_t off = SWZ(p2, (qh * 16 + i) * 4);
            *(uint32_t*)(sm + off) = hi;
            *(uint32_t*)(sm + 8192 + off) = lo;
        }
    }
    __syncthreads();

    // ---- A frags = B-matrix rows (channels)
    uint32_t ah[4][4], alf[4][4];
    {
        int arow = wid * 16 + (lane & 15);
#pragma unroll
        for (int k = 0; k < 4; k++) {
            uint32_t cb = k * 32 + (lane >> 4) * 16;
            uint32_t off = SWZ(arow, cb);
            ldmx4(ah[k], base + 16384 + off);
            ldmx4(alf[k], base + 24576 + off);
        }
    }

    int c0base = wid * 16;
#pragma unroll 2
    for (int nt = 0; nt < 8; nt++) {
        float d[4] = {0.f, 0.f, 0.f, 0.f};
        int prow = nt * 8 + (lane & 7);
#pragma unroll
        for (int k = 0; k < 4; k++) {
            uint32_t cb = k * 32 + ((lane >> 3) & 1) * 16;
            uint32_t off = SWZ(prow, cb);
            uint32_t qf[2], ql[2];
            ldmx2(qf, base + off);
            mma16816(d, ah[k], qf);
            mma16816(d, alf[k], qf);
            ldmx2(ql, base + 8192 + off);
            mma16816(d, ah[k], ql);
        }
        int c0 = c0base + (lane >> 2);
        int col = nt * 8 + 2 * (lane & 3);
        float b0 = bias_s[c0], b1 = bias_s[c0 + 8];
        *(float2*)(out + ((size_t)(n * 64 + c0)) * SS + sIn + col) =
            make_float2(d[0] + b0, d[1] + b0);
        *(float2*)(out + ((size_t)(n * 64 + c0 + 8)) * SS + sIn + col) =
            make_float2(d[2] + b1, d[3] + b1);
    }
}

// ---------------- launch ----------------
extern "C" void kernel_launch(void* const* d_in, const int* in_sizes, int n_in,
                              void* d_out, int out_size) {
    const float* x   = (const float*)d_in[0];
    const float* kow = (const float*)d_in[1];
    const float* kob = (const float*)d_in[2];
    const float* kw  = (const float*)d_in[3];
    const float* qow = (const float*)d_in[4];
    const float* qob = (const float*)d_in[5];
    const float* qw  = (const float*)d_in[6];
    const float* vow = (const float*)d_in[7];
    const float* vob = (const float*)d_in[8];
    const float* vw  = (const float*)d_in[9];
    const float* rpw = (const float*)d_in[10];
    const float* rpb = (const float*)d_in[11];
    float* out = (float*)d_out;

    k_wprep<<<24, 256>>>(kw, qw, vw);
    k_a<<<NS / 64, 128>>>(x, kow, kob, qow, qob, vow, vob);
    k_b<<<1024, 256>>>();
    k_red2<<<544, 256>>>();
    k_fold2<<<32, 256>>>(rpw);
    k_c<<<NS / 64, 128>>>(rpb, out);
}